// round 5
// baseline (speedup 1.0000x reference)
#include <cuda_runtime.h>
#include <cuda_bf16.h>
#include <math.h>
#include <stdint.h>

#define BB   128
#define LL   1024
#define DK   128
#define DV   256
#define HH   256
#define NN   50
#define MM   (BB * LL)   // 131072 rows

typedef unsigned long long u64;

// ---------------- packed f32x2 helpers ----------------
__device__ __forceinline__ u64 fma2(u64 a, u64 b, u64 c) {
    u64 d; asm("fma.rn.f32x2 %0, %1, %2, %3;" : "=l"(d) : "l"(a), "l"(b), "l"(c)); return d;
}
__device__ __forceinline__ u64 add2(u64 a, u64 b) {
    u64 d; asm("add.rn.f32x2 %0, %1, %2;" : "=l"(d) : "l"(a), "l"(b)); return d;
}
__device__ __forceinline__ u64 pack2(float lo, float hi) {
    u64 r; asm("mov.b64 %0, {%1, %2};" : "=l"(r) : "f"(lo), "f"(hi)); return r;
}
__device__ __forceinline__ float2 unpack2(u64 v) {
    float2 r; asm("mov.b64 {%0, %1}, %2;" : "=f"(r.x), "=f"(r.y) : "l"(v)); return r;
}

// ---------------- async / smem helpers ----------------
__device__ __forceinline__ uint32_t smem_u32(const void* p) {
    uint32_t a;
    asm("{ .reg .u64 t; cvta.to.shared.u64 t, %1; cvt.u32.u64 %0, t; }" : "=r"(a) : "l"(p));
    return a;
}
__device__ __forceinline__ void cpasync16(uint32_t saddr, const void* gptr) {
    asm volatile("cp.async.cg.shared.global [%0], [%1], 16;" :: "r"(saddr), "l"(gptr) : "memory");
}
__device__ __forceinline__ void cpasync4(uint32_t saddr, const void* gptr) {
    asm volatile("cp.async.ca.shared.global [%0], [%1], 4;" :: "r"(saddr), "l"(gptr) : "memory");
}
__device__ __forceinline__ uint32_t lds32(uint32_t addr) {
    uint32_t v; asm volatile("ld.shared.b32 %0, [%1];" : "=r"(v) : "r"(addr)); return v;
}
__device__ __forceinline__ void mma16816(float* c, const uint32_t* a, const uint32_t* b) {
    asm volatile(
        "mma.sync.aligned.m16n8k16.row.col.f32.bf16.bf16.f32 "
        "{%0,%1,%2,%3}, {%4,%5,%6,%7}, {%8,%9}, {%0,%1,%2,%3};"
        : "+f"(c[0]), "+f"(c[1]), "+f"(c[2]), "+f"(c[3])
        : "r"(a[0]), "r"(a[1]), "r"(a[2]), "r"(a[3]), "r"(b[0]), "r"(b[1]));
}
__device__ __forceinline__ uint32_t bfpair(float x, float y) {
    __nv_bfloat16 bx = __float2bfloat16(x), by = __float2bfloat16(y);
    return ((uint32_t)__bfloat16_as_ushort(by) << 16) | __bfloat16_as_ushort(bx);
}

// ------------------------- scratch (device globals; no allocs) -------------------------
__device__ float          g_e[(size_t)MM * DV];
__device__ float          g_a[(size_t)MM * DV];
__device__ float          g_read[(size_t)MM * DV];
__device__ float          g_score[(size_t)MM * NN];
__device__ __nv_bfloat16  g_wehi[DV * DV], g_welo[DV * DV];
__device__ __nv_bfloat16  g_wahi[DV * DV], g_walo[DV * DV];
__device__ __nv_bfloat16  g_wohi[HH * (DV + DK)], g_wolo[HH * (DV + DK)];

// =======================================================================================
// Weight f32 -> bf16 hi/lo split (tiny, runs once per weight matrix)
// =======================================================================================
__global__ void __launch_bounds__(256) conv_kernel(const float* __restrict__ x,
                                                   __nv_bfloat16* __restrict__ hi,
                                                   __nv_bfloat16* __restrict__ lo,
                                                   int n)
{
    int i = blockIdx.x * 256 + threadIdx.x;
    if (i >= n) return;
    float v = x[i];
    __nv_bfloat16 h = __float2bfloat16(v);
    hi[i] = h;
    lo[i] = __float2bfloat16(v - __bfloat162float(h));
}

// =======================================================================================
// score = softmax(problems @ w_key^T) over n=50 (packed f32x2 along K)
// =======================================================================================
__global__ void __launch_bounds__(256) score_kernel(const float* __restrict__ P,
                                                    const float* __restrict__ Wk,
                                                    float* __restrict__ S)
{
    __shared__ float ws[NN * DK];
    int tid = threadIdx.x;
    for (int i = tid; i < NN * DK; i += 256) ws[i] = Wk[i];
    __syncthreads();

    int row = blockIdx.x * 256 + tid;
    const float4* xp = reinterpret_cast<const float4*>(P + (size_t)row * DK);

    u64 acc2[NN];
#pragma unroll
    for (int n = 0; n < NN; ++n) acc2[n] = 0ull;

    for (int k4 = 0; k4 < DK / 4; ++k4) {
        float4 x = xp[k4];
        u64 x01 = pack2(x.x, x.y);
        u64 x23 = pack2(x.z, x.w);
#pragma unroll
        for (int n = 0; n < NN; ++n) {
            const u64* wrow = reinterpret_cast<const u64*>(&ws[n * DK]);
            acc2[n] = fma2(x01, wrow[k4 * 2 + 0], acc2[n]);
            acc2[n] = fma2(x23, wrow[k4 * 2 + 1], acc2[n]);
        }
    }

    float acc[NN];
#pragma unroll
    for (int n = 0; n < NN; ++n) { float2 v = unpack2(acc2[n]); acc[n] = v.x + v.y; }

    float mx = -1e30f;
#pragma unroll
    for (int n = 0; n < NN; ++n) mx = fmaxf(mx, acc[n]);
    float sum = 0.f;
#pragma unroll
    for (int n = 0; n < NN; ++n) { acc[n] = expf(acc[n] - mx); sum += acc[n]; }
    float inv = 1.f / sum;
    float* op = S + (size_t)row * NN;
#pragma unroll
    for (int n = 0; n < NN; ++n) op[n] = acc[n] * inv;
}

// =======================================================================================
// HMMA hi/lo 3-pass GEMM with FUSED f32->bf16 split on the A operand.
// A is f32 (two K-concatenated sources split at k1len); W is pre-split bf16 hi/lo.
// CTA tile 128x128, warp tile 32x64, K-chunk 32.
// Dual-target: n-blocks [0,nsplit) -> (w0,b0,C0,act0); rest -> (w1,b1,C1,act1).
// Grid: x = n-blocks (fast-varying => A stays in L2 across n-blocks of one m-block).
// =======================================================================================
#define MATB 10240u    // bytes per bf16 matrix tile (128 rows * 80B pitch)
#define BUFB 40960u    // per double-buffer stage: Ahi, Alo, Bhi, Blo

__global__ void __launch_bounds__(256)
gemm_fused(const float* __restrict__ a1, int lda1, int k1len,
           const float* __restrict__ a2, int lda2, int K,
           const __nv_bfloat16* __restrict__ w0hi, const __nv_bfloat16* __restrict__ w0lo,
           const float* __restrict__ b0, float* __restrict__ C0, int act0,
           const __nv_bfloat16* __restrict__ w1hi, const __nv_bfloat16* __restrict__ w1lo,
           const float* __restrict__ b1, float* __restrict__ C1, int act1,
           int nsplit)
{
    extern __shared__ __align__(16) char dsm[];
    const uint32_t dbase = smem_u32(dsm);

    const int tid = threadIdx.x;
    const int m0 = blockIdx.y * 128;
    const int nb = blockIdx.x;

    const __nv_bfloat16 *whi, *wlo; const float* bias; float* C; int act, nloc;
    if (nb < nsplit) { whi = w0hi; wlo = w0lo; bias = b0; C = C0; act = act0; nloc = nb * 128; }
    else             { whi = w1hi; wlo = w1lo; bias = b1; C = C1; act = act1; nloc = (nb - nsplit) * 128; }

    const int wid = tid >> 5;
    const int lane = tid & 31;
    const int g  = lane >> 2;
    const int t2 = (lane & 3) * 2;
    const int warpM = (wid & 3) * 32;
    const int warpN = (wid >> 2) * 64;

    // A producer mapping: thread -> row (tid>>1), 16 cols at (tid&1)*16
    const int arow = tid >> 1;
    const int acol = (tid & 1) * 16;

    const int nch = K / 32;

    auto ldgA = [&](int c, float4* av) {
        int k0 = c * 32;
        const float* src; int ld, kk;
        if (k0 < k1len) { src = a1; ld = lda1; kk = k0; }
        else            { src = a2; ld = lda2; kk = k0 - k1len; }
        const float4* p = reinterpret_cast<const float4*>(&src[(size_t)(m0 + arow) * ld + kk + acol]);
        av[0] = p[0]; av[1] = p[1]; av[2] = p[2]; av[3] = p[3];
    };
    auto stsA = [&](int c, const float4* av) {
        uint32_t sb = dbase + (uint32_t)(c & 1) * BUFB;
        uint32_t base = sb + (uint32_t)(arow * 80 + acol * 2);
        uint4 h0, h1, l0, l1;
        const float* f = reinterpret_cast<const float*>(av);
        uint32_t hp[8], lp[8];
#pragma unroll
        for (int q = 0; q < 8; ++q) {
            float x = f[2 * q], y = f[2 * q + 1];
            __nv_bfloat16 hx = __float2bfloat16(x), hy = __float2bfloat16(y);
            hp[q] = ((uint32_t)__bfloat16_as_ushort(hy) << 16) | __bfloat16_as_ushort(hx);
            lp[q] = bfpair(x - __bfloat162float(hx), y - __bfloat162float(hy));
        }
        h0 = make_uint4(hp[0], hp[1], hp[2], hp[3]);
        h1 = make_uint4(hp[4], hp[5], hp[6], hp[7]);
        l0 = make_uint4(lp[0], lp[1], lp[2], lp[3]);
        l1 = make_uint4(lp[4], lp[5], lp[6], lp[7]);
        asm volatile("st.shared.v4.b32 [%0], {%1,%2,%3,%4};" :: "r"(base), "r"(h0.x), "r"(h0.y), "r"(h0.z), "r"(h0.w) : "memory");
        asm volatile("st.shared.v4.b32 [%0], {%1,%2,%3,%4};" :: "r"(base + 16), "r"(h1.x), "r"(h1.y), "r"(h1.z), "r"(h1.w) : "memory");
        asm volatile("st.shared.v4.b32 [%0], {%1,%2,%3,%4};" :: "r"(base + MATB), "r"(l0.x), "r"(l0.y), "r"(l0.z), "r"(l0.w) : "memory");
        asm volatile("st.shared.v4.b32 [%0], {%1,%2,%3,%4};" :: "r"(base + MATB + 16), "r"(l1.x), "r"(l1.y), "r"(l1.z), "r"(l1.w) : "memory");
    };
    auto cpB = [&](int c) {
        uint32_t sb = dbase + (uint32_t)(c & 1) * BUFB;
        int k0 = c * 32;
#pragma unroll
        for (int i = 0; i < 2; ++i) {
            int gidx = tid + 256 * i;            // 0..511
            int row = gidx >> 2, seg = gidx & 3;
            uint32_t so = (uint32_t)(row * 80 + seg * 16);
            size_t gB = (size_t)(nloc + row) * K + k0 + seg * 8;
            cpasync16(sb + 2 * MATB + so, whi + gB);
            cpasync16(sb + 3 * MATB + so, wlo + gB);
        }
        asm volatile("cp.async.commit_group;" ::: "memory");
    };

    float acc[2][8][4];
#pragma unroll
    for (int mt = 0; mt < 2; ++mt)
#pragma unroll
        for (int nt = 0; nt < 8; ++nt)
#pragma unroll
            for (int q = 0; q < 4; ++q) acc[mt][nt][q] = 0.f;

    float4 av[4];
    ldgA(0, av);
    cpB(0);

    for (int c = 0; c < nch; ++c) {
        asm volatile("cp.async.wait_group 0;" ::: "memory");
        stsA(c, av);
        __syncthreads();
        if (c + 1 < nch) {
            cpB(c + 1);
            ldgA(c + 1, av);
        }

        uint32_t sb = dbase + (uint32_t)(c & 1) * BUFB;
#pragma unroll
        for (int ks = 0; ks < 2; ++ks) {
            const uint32_t cb = (uint32_t)((ks * 16 + t2) * 2);
            uint32_t a_h[2][4], a_l[2][4];
#pragma unroll
            for (int mt = 0; mt < 2; ++mt) {
                uint32_t r0 = sb + (uint32_t)((warpM + mt * 16 + g) * 80) + cb;
                uint32_t r8 = r0 + 8 * 80;
                a_h[mt][0] = lds32(r0);        a_h[mt][1] = lds32(r8);
                a_h[mt][2] = lds32(r0 + 16);   a_h[mt][3] = lds32(r8 + 16);
                a_l[mt][0] = lds32(r0 + MATB); a_l[mt][1] = lds32(r8 + MATB);
                a_l[mt][2] = lds32(r0 + MATB + 16); a_l[mt][3] = lds32(r8 + MATB + 16);
            }
            uint32_t b_h[8][2], b_l[8][2];
#pragma unroll
            for (int nt = 0; nt < 8; ++nt) {
                uint32_t rr = sb + 2 * MATB + (uint32_t)((warpN + nt * 8 + g) * 80) + cb;
                b_h[nt][0] = lds32(rr);        b_h[nt][1] = lds32(rr + 16);
                b_l[nt][0] = lds32(rr + MATB); b_l[nt][1] = lds32(rr + MATB + 16);
            }
#pragma unroll
            for (int mt = 0; mt < 2; ++mt)
#pragma unroll
                for (int nt = 0; nt < 8; ++nt) {
                    mma16816(acc[mt][nt], a_h[mt], b_h[nt]);
                    mma16816(acc[mt][nt], a_h[mt], b_l[nt]);
                    mma16816(acc[mt][nt], a_l[mt], b_h[nt]);
                }
        }
        __syncthreads();
    }

    // epilogue: bias + activation, STG.64 per quad-sector
#pragma unroll
    for (int mt = 0; mt < 2; ++mt) {
        int r0 = m0 + warpM + mt * 16 + g;
#pragma unroll
        for (int nt = 0; nt < 8; ++nt) {
            int cc = nloc + warpN + nt * 8 + t2;
            float bb0 = bias[cc], bb1 = bias[cc + 1];
            float v0 = acc[mt][nt][0] + bb0, v1 = acc[mt][nt][1] + bb1;
            float v2 = acc[mt][nt][2] + bb0, v3 = acc[mt][nt][3] + bb1;
            if (act == 0) {
                v0 = __fdividef(1.f, 1.f + __expf(-v0));
                v1 = __fdividef(1.f, 1.f + __expf(-v1));
                v2 = __fdividef(1.f, 1.f + __expf(-v2));
                v3 = __fdividef(1.f, 1.f + __expf(-v3));
            } else {
                v0 = tanhf(v0); v1 = tanhf(v1); v2 = tanhf(v2); v3 = tanhf(v3);
            }
            *reinterpret_cast<float2*>(&C[(size_t)r0 * 256 + cc])       = make_float2(v0, v1);
            *reinterpret_cast<float2*>(&C[(size_t)(r0 + 8) * 256 + cc]) = make_float2(v2, v3);
        }
    }
}

// =======================================================================================
// Scan: 256 threads/CTA (thread = column d), slots packed in 25 f32x2 pairs.
// Score staging via 4-deep cp.async ring; e/a via depth-3 register pipeline.
// Emits plain f32 reads (consumed by the fused-convert out-GEMM).
// =======================================================================================
__global__ void __launch_bounds__(256) scan_kernel(const float* __restrict__ S,
                                                   const float* __restrict__ E,
                                                   const float* __restrict__ A,
                                                   const float* __restrict__ M0,
                                                   float* __restrict__ R)
{
    const int b = blockIdx.x;
    const int d = threadIdx.x;
    __shared__ __align__(16) float ring[4][52];

    u64 m[25];
#pragma unroll
    for (int j = 0; j < 25; ++j)
        m[j] = pack2(M0[(2 * j) * DV + d], M0[(2 * j + 1) * DV + d]);

    const float* sp = S + (size_t)b * LL * NN;
    const float* ep = E + (size_t)b * LL * DV + d;
    const float* ap = A + (size_t)b * LL * DV + d;
    float*       rp = R + (size_t)b * LL * DV + d;

    if (d < NN) {
#pragma unroll
        for (int p = 0; p < 3; ++p) {
            cpasync4(smem_u32(&ring[p][d]), sp + (size_t)p * NN + d);
            asm volatile("cp.async.commit_group;" ::: "memory");
        }
        asm volatile("cp.async.wait_group 2;" ::: "memory");
    }
    float e0 = ep[0],      a0 = ap[0];
    float e1 = ep[DV],     a1 = ap[DV];
    float e2 = ep[2 * DV], a2 = ap[2 * DV];
    __syncthreads();

    for (int l = 0; l < LL; ++l) {
        const int n3 = (l + 3 < LL) ? (l + 3) : (LL - 1);
        if (d < NN) {
            cpasync4(smem_u32(&ring[(l + 3) & 3][d]), sp + (size_t)n3 * NN + d);
            asm volatile("cp.async.commit_group;" ::: "memory");
        }
        float en = ep[(size_t)n3 * DV];
        float an = ap[(size_t)n3 * DV];

        u64 apk  = pack2(a0, a0);
        u64 nepk = pack2(-e0, -e0);
        u64 r0 = 0ull, r1 = 0ull;
        const u64* sb = reinterpret_cast<const u64*>(ring[l & 3]);
#pragma unroll
        for (int j = 0; j < 25; ++j) {
            u64 spk = sb[j];                  // LDS.64 broadcast
            if (j & 1) r1 = fma2(spk, m[j], r1);
            else       r0 = fma2(spk, m[j], r0);
            u64 tt = fma2(nepk, m[j], apk);   // a - e*m
            m[j] = fma2(spk, tt, m[j]);       // m += s*(a - e*m)
        }
        float2 rv = unpack2(add2(r0, r1));
        rp[(size_t)l * DV] = rv.x + rv.y;

        if (d < NN) asm volatile("cp.async.wait_group 2;" ::: "memory");
        __syncthreads();
        e0 = e1; a0 = a1; e1 = e2; a1 = a2; e2 = en; a2 = an;
    }
}

// =======================================================================================
// Launch
// =======================================================================================
extern "C" void kernel_launch(void* const* d_in, const int* in_sizes, int n_in,
                              void* d_out, int out_size)
{
    const float* problems     = (const float*)d_in[0];
    const float* interactions = (const float*)d_in[1];
    const float* w_key        = (const float*)d_in[2];
    const float* w_erase_w    = (const float*)d_in[3];
    const float* w_erase_b    = (const float*)d_in[4];
    const float* w_add_w      = (const float*)d_in[5];
    const float* w_add_b      = (const float*)d_in[6];
    const float* w_out_w      = (const float*)d_in[7];
    const float* w_out_b      = (const float*)d_in[8];
    const float* init_memory  = (const float*)d_in[9];
    float* out = (float*)d_out;

    float *ge, *ga, *gr, *gs;
    __nv_bfloat16 *wehi, *welo, *wahi, *walo, *wohi, *wolo;
    cudaGetSymbolAddress((void**)&ge,   g_e);
    cudaGetSymbolAddress((void**)&ga,   g_a);
    cudaGetSymbolAddress((void**)&gr,   g_read);
    cudaGetSymbolAddress((void**)&gs,   g_score);
    cudaGetSymbolAddress((void**)&wehi, g_wehi);  cudaGetSymbolAddress((void**)&welo, g_welo);
    cudaGetSymbolAddress((void**)&wahi, g_wahi);  cudaGetSymbolAddress((void**)&walo, g_walo);
    cudaGetSymbolAddress((void**)&wohi, g_wohi);  cudaGetSymbolAddress((void**)&wolo, g_wolo);

    cudaFuncSetAttribute(gemm_fused, cudaFuncAttributeMaxDynamicSharedMemorySize, 2 * BUFB);

    // weight hi/lo splits (tiny)
    conv_kernel<<<(DV * DV + 255) / 256, 256>>>(w_erase_w, wehi, welo, DV * DV);
    conv_kernel<<<(DV * DV + 255) / 256, 256>>>(w_add_w, wahi, walo, DV * DV);
    conv_kernel<<<(HH * (DV + DK) + 255) / 256, 256>>>(w_out_w, wohi, wolo, HH * (DV + DK));

    // attention scores
    score_kernel<<<MM / 256, 256>>>(problems, w_key, gs);

    // fused gate GEMMs (e: n-blocks 0-1, a: n-blocks 2-3); A = interactions f32
    dim3 gg(4, MM / 128);
    gemm_fused<<<gg, 256, 2 * BUFB>>>(interactions, DV, DV, interactions, DV, DV,
                                      wehi, welo, w_erase_b, ge, /*sigmoid*/0,
                                      wahi, walo, w_add_b,   ga, /*tanh*/1, 2);

    // sequential memory scan
    scan_kernel<<<BB, 256>>>(gs, ge, ga, init_memory, gr);

    // output GEMM: A = [reads f32 (256) | problems f32 (128)], K = 384
    dim3 go(2, MM / 128);
    gemm_fused<<<go, 256, 2 * BUFB>>>(gr, DV, DV, problems, DK, DV + DK,
                                      wohi, wolo, w_out_b, out, /*tanh*/1,
                                      wohi, wolo, w_out_b, out, 1, 2);
}

// round 6
// speedup vs baseline: 1.1344x; 1.1344x over previous
#include <cuda_runtime.h>
#include <cuda_bf16.h>
#include <math.h>
#include <stdint.h>

#define BB   128
#define LL   1024
#define DK   128
#define DV   256
#define HH   256
#define NN   50
#define MM   (BB * LL)   // 131072 rows

typedef unsigned long long u64;

// ---------------- packed f32x2 helpers ----------------
__device__ __forceinline__ u64 fma2(u64 a, u64 b, u64 c) {
    u64 d; asm("fma.rn.f32x2 %0, %1, %2, %3;" : "=l"(d) : "l"(a), "l"(b), "l"(c)); return d;
}
__device__ __forceinline__ u64 add2(u64 a, u64 b) {
    u64 d; asm("add.rn.f32x2 %0, %1, %2;" : "=l"(d) : "l"(a), "l"(b)); return d;
}
__device__ __forceinline__ u64 pack2(float lo, float hi) {
    u64 r; asm("mov.b64 %0, {%1, %2};" : "=l"(r) : "f"(lo), "f"(hi)); return r;
}
__device__ __forceinline__ float2 unpack2(u64 v) {
    float2 r; asm("mov.b64 {%0, %1}, %2;" : "=f"(r.x), "=f"(r.y) : "l"(v)); return r;
}

// ---------------- async / smem helpers ----------------
__device__ __forceinline__ uint32_t smem_u32(const void* p) {
    uint32_t a;
    asm("{ .reg .u64 t; cvta.to.shared.u64 t, %1; cvt.u32.u64 %0, t; }" : "=r"(a) : "l"(p));
    return a;
}
__device__ __forceinline__ void cpasync16(uint32_t saddr, const void* gptr) {
    asm volatile("cp.async.cg.shared.global [%0], [%1], 16;" :: "r"(saddr), "l"(gptr) : "memory");
}
__device__ __forceinline__ void cpasync4(uint32_t saddr, const void* gptr) {
    asm volatile("cp.async.ca.shared.global [%0], [%1], 4;" :: "r"(saddr), "l"(gptr) : "memory");
}
__device__ __forceinline__ uint32_t lds32(uint32_t addr) {
    uint32_t v; asm volatile("ld.shared.b32 %0, [%1];" : "=r"(v) : "r"(addr)); return v;
}
__device__ __forceinline__ void mma16816(float* c, const uint32_t* a, const uint32_t* b) {
    asm volatile(
        "mma.sync.aligned.m16n8k16.row.col.f32.bf16.bf16.f32 "
        "{%0,%1,%2,%3}, {%4,%5,%6,%7}, {%8,%9}, {%0,%1,%2,%3};"
        : "+f"(c[0]), "+f"(c[1]), "+f"(c[2]), "+f"(c[3])
        : "r"(a[0]), "r"(a[1]), "r"(a[2]), "r"(a[3]), "r"(b[0]), "r"(b[1]));
}

// ------------------------- scratch (device globals; no allocs) -------------------------
__device__ float          g_e[(size_t)MM * DV];
__device__ float          g_a[(size_t)MM * DV];
__device__ float          g_score[(size_t)MM * NN];
__device__ __nv_bfloat16  g_ibhi[(size_t)MM * DV], g_iblo[(size_t)MM * DV];   // interactions
__device__ __nv_bfloat16  g_pbhi[(size_t)MM * DK], g_pblo[(size_t)MM * DK];   // problems
__device__ __nv_bfloat16  g_rhi[(size_t)MM * DV],  g_rlo[(size_t)MM * DV];    // scan reads
__device__ __nv_bfloat16  g_wehi[DV * DV], g_welo[DV * DV];
__device__ __nv_bfloat16  g_wahi[DV * DV], g_walo[DV * DV];
__device__ __nv_bfloat16  g_wohi[HH * (DV + DK)], g_wolo[HH * (DV + DK)];
__device__ __nv_bfloat16  g_wkhi[64 * DK], g_wklo[64 * DK];   // w_key padded to 64 rows (rest stays 0)

// =======================================================================================
// f32 -> bf16 hi/lo split conversion (vectorized by 4)
// =======================================================================================
__global__ void __launch_bounds__(256) conv_kernel(const float* __restrict__ x,
                                                   __nv_bfloat16* __restrict__ hi,
                                                   __nv_bfloat16* __restrict__ lo,
                                                   int n4)
{
    int i = blockIdx.x * 256 + threadIdx.x;
    if (i >= n4) return;
    float4 v = reinterpret_cast<const float4*>(x)[i];
    ushort4 h, l;
    __nv_bfloat16 b; float f;
    b = __float2bfloat16(v.x); h.x = __bfloat16_as_ushort(b); f = v.x - __bfloat162float(b);
    l.x = __bfloat16_as_ushort(__float2bfloat16(f));
    b = __float2bfloat16(v.y); h.y = __bfloat16_as_ushort(b); f = v.y - __bfloat162float(b);
    l.y = __bfloat16_as_ushort(__float2bfloat16(f));
    b = __float2bfloat16(v.z); h.z = __bfloat16_as_ushort(b); f = v.z - __bfloat162float(b);
    l.z = __bfloat16_as_ushort(__float2bfloat16(f));
    b = __float2bfloat16(v.w); h.w = __bfloat16_as_ushort(b); f = v.w - __bfloat162float(b);
    l.w = __bfloat16_as_ushort(__float2bfloat16(f));
    reinterpret_cast<ushort4*>(hi)[i] = h;
    reinterpret_cast<ushort4*>(lo)[i] = l;
}

// =======================================================================================
// HMMA score GEMM + softmax epilogue.
// logits = P @ Wk^T (N padded to 64, hi/lo 3-pass), softmax over n<50 per row,
// row reduction via quad shfl.bfly. CTA tile 128x64, 4 warps (warp tile 32x64).
// =======================================================================================
#define SGP   80u       // row pitch bytes
#define SMATA 10240u    // A tile bytes (128*80)
#define SMATB 5120u     // B tile bytes (64*80)
#define SBUF  30720u    // stage: Ahi, Alo, Bhi, Blo

__global__ void __launch_bounds__(128)
score_hmma(const __nv_bfloat16* __restrict__ phi, const __nv_bfloat16* __restrict__ plo,
           const __nv_bfloat16* __restrict__ wkhi, const __nv_bfloat16* __restrict__ wklo,
           float* __restrict__ S)
{
    extern __shared__ __align__(16) char dsm[];
    const uint32_t dbase = smem_u32(dsm);

    const int tid = threadIdx.x;
    const int m0 = blockIdx.x * 128;
    const int wid = tid >> 5;
    const int lane = tid & 31;
    const int g  = lane >> 2;
    const int t2 = (lane & 3) * 2;
    const int warpM = wid * 32;

    auto load_chunk = [&](int c) {
        uint32_t sb = dbase + (uint32_t)(c & 1) * SBUF;
        int k0 = c * 32;
#pragma unroll
        for (int i = 0; i < 4; ++i) {
            int idx = tid + 128 * i;             // 0..511
            int row = idx >> 2, seg = idx & 3;
            uint32_t so = (uint32_t)(row * 80 + seg * 16);
            size_t gA = (size_t)(m0 + row) * DK + k0 + seg * 8;
            cpasync16(sb + so,         phi + gA);
            cpasync16(sb + SMATA + so, plo + gA);
        }
#pragma unroll
        for (int i = 0; i < 2; ++i) {
            int idx = tid + 128 * i;             // 0..255
            int row = idx >> 2, seg = idx & 3;
            uint32_t so = (uint32_t)(row * 80 + seg * 16);
            size_t gB = (size_t)row * DK + k0 + seg * 8;
            cpasync16(sb + 2 * SMATA + so,         wkhi + gB);
            cpasync16(sb + 2 * SMATA + SMATB + so, wklo + gB);
        }
        asm volatile("cp.async.commit_group;" ::: "memory");
    };

    float acc[2][8][4];
#pragma unroll
    for (int mt = 0; mt < 2; ++mt)
#pragma unroll
        for (int nt = 0; nt < 8; ++nt)
#pragma unroll
            for (int q = 0; q < 4; ++q) acc[mt][nt][q] = 0.f;

    load_chunk(0);

    for (int c = 0; c < 4; ++c) {
        if (c + 1 < 4) {
            load_chunk(c + 1);
            asm volatile("cp.async.wait_group 1;" ::: "memory");
        } else {
            asm volatile("cp.async.wait_group 0;" ::: "memory");
        }
        __syncthreads();

        uint32_t sb = dbase + (uint32_t)(c & 1) * SBUF;
#pragma unroll
        for (int ks = 0; ks < 2; ++ks) {
            const uint32_t cb = (uint32_t)((ks * 16 + t2) * 2);
            uint32_t a_h[2][4], a_l[2][4];
#pragma unroll
            for (int mt = 0; mt < 2; ++mt) {
                uint32_t r0 = sb + (uint32_t)((warpM + mt * 16 + g) * 80) + cb;
                uint32_t r8 = r0 + 8 * 80;
                a_h[mt][0] = lds32(r0);         a_h[mt][1] = lds32(r8);
                a_h[mt][2] = lds32(r0 + 16);    a_h[mt][3] = lds32(r8 + 16);
                a_l[mt][0] = lds32(r0 + SMATA); a_l[mt][1] = lds32(r8 + SMATA);
                a_l[mt][2] = lds32(r0 + SMATA + 16); a_l[mt][3] = lds32(r8 + SMATA + 16);
            }
            uint32_t b_h[8][2], b_l[8][2];
#pragma unroll
            for (int nt = 0; nt < 8; ++nt) {
                uint32_t rr = sb + 2 * SMATA + (uint32_t)((nt * 8 + g) * 80) + cb;
                b_h[nt][0] = lds32(rr);          b_h[nt][1] = lds32(rr + 16);
                b_l[nt][0] = lds32(rr + SMATB);  b_l[nt][1] = lds32(rr + SMATB + 16);
            }
#pragma unroll
            for (int mt = 0; mt < 2; ++mt)
#pragma unroll
                for (int nt = 0; nt < 8; ++nt) {
                    mma16816(acc[mt][nt], a_h[mt], b_h[nt]);
                    mma16816(acc[mt][nt], a_h[mt], b_l[nt]);
                    mma16816(acc[mt][nt], a_l[mt], b_h[nt]);
                }
        }
        __syncthreads();
    }

    // softmax epilogue: per (mt, half) row, 16 local cols; quad reduce via shfl.bfly
#pragma unroll
    for (int mt = 0; mt < 2; ++mt) {
#pragma unroll
        for (int hf = 0; hf < 2; ++hf) {
            int row = m0 + warpM + mt * 16 + g + hf * 8;
            float v[16];
#pragma unroll
            for (int nt = 0; nt < 8; ++nt) {
                int c0 = nt * 8 + t2;
                v[2 * nt]     = (c0     < NN) ? acc[mt][nt][2 * hf]     : -1e30f;
                v[2 * nt + 1] = (c0 + 1 < NN) ? acc[mt][nt][2 * hf + 1] : -1e30f;
            }
            float mx = v[0];
#pragma unroll
            for (int q = 1; q < 16; ++q) mx = fmaxf(mx, v[q]);
            mx = fmaxf(mx, __shfl_xor_sync(0xffffffffu, mx, 1));
            mx = fmaxf(mx, __shfl_xor_sync(0xffffffffu, mx, 2));
            float sum = 0.f;
#pragma unroll
            for (int q = 0; q < 16; ++q) { v[q] = __expf(v[q] - mx); sum += v[q]; }
            sum += __shfl_xor_sync(0xffffffffu, sum, 1);
            sum += __shfl_xor_sync(0xffffffffu, sum, 2);
            float inv = __fdividef(1.f, sum);
            float* op = S + (size_t)row * NN;
#pragma unroll
            for (int nt = 0; nt < 8; ++nt) {
                int c0 = nt * 8 + t2;
                if (c0 < NN)
                    *reinterpret_cast<float2*>(op + c0) =
                        make_float2(v[2 * nt] * inv, v[2 * nt + 1] * inv);
            }
        }
    }
}

// =======================================================================================
// HMMA bf16 hi/lo 3-pass GEMM (R4-proven): C = act(A @ W^T + bias).
// CTA tile 128x128, warp tile 32x64, K-chunk 32, cp.async double buffer.
// =======================================================================================
#define MATB 10240u
#define BUFB 40960u

__global__ void __launch_bounds__(256)
gemm_hmma(const __nv_bfloat16* __restrict__ a1hi, const __nv_bfloat16* __restrict__ a1lo,
          int lda1, int k1len,
          const __nv_bfloat16* __restrict__ a2hi, const __nv_bfloat16* __restrict__ a2lo,
          int lda2,
          const __nv_bfloat16* __restrict__ bhi, const __nv_bfloat16* __restrict__ blo,
          int K,
          const float* __restrict__ bias, float* __restrict__ C, int act)
{
    extern __shared__ __align__(16) char dsm[];
    const uint32_t dbase = smem_u32(dsm);

    const int tid = threadIdx.x;
    const int m0 = blockIdx.x * 128;
    const int n0 = blockIdx.y * 128;
    const int wid = tid >> 5;
    const int lane = tid & 31;
    const int g  = lane >> 2;
    const int t2 = (lane & 3) * 2;
    const int warpM = (wid & 3) * 32;
    const int warpN = (wid >> 2) * 64;

    const int nch = K / 32;

    auto load_chunk = [&](int c) {
        uint32_t sb = dbase + (uint32_t)(c & 1) * BUFB;
        int k0 = c * 32;
        const __nv_bfloat16 *shi, *slo; int ld, kk;
        if (k0 < k1len) { shi = a1hi; slo = a1lo; ld = lda1; kk = k0; }
        else            { shi = a2hi; slo = a2lo; ld = lda2; kk = k0 - k1len; }
#pragma unroll
        for (int i = 0; i < 2; ++i) {
            int gidx = tid + 256 * i;
            int row = gidx >> 2, seg = gidx & 3;
            uint32_t so = (uint32_t)(row * 80 + seg * 16);
            size_t gA = (size_t)(m0 + row) * ld + kk + seg * 8;
            cpasync16(sb + so,            shi + gA);
            cpasync16(sb + MATB + so,     slo + gA);
            size_t gB = (size_t)(n0 + row) * K + k0 + seg * 8;
            cpasync16(sb + 2 * MATB + so, bhi + gB);
            cpasync16(sb + 3 * MATB + so, blo + gB);
        }
        asm volatile("cp.async.commit_group;" ::: "memory");
    };

    float acc[2][8][4];
#pragma unroll
    for (int mt = 0; mt < 2; ++mt)
#pragma unroll
        for (int nt = 0; nt < 8; ++nt)
#pragma unroll
            for (int q = 0; q < 4; ++q) acc[mt][nt][q] = 0.f;

    load_chunk(0);

    for (int c = 0; c < nch; ++c) {
        if (c + 1 < nch) {
            load_chunk(c + 1);
            asm volatile("cp.async.wait_group 1;" ::: "memory");
        } else {
            asm volatile("cp.async.wait_group 0;" ::: "memory");
        }
        __syncthreads();

        uint32_t sb = dbase + (uint32_t)(c & 1) * BUFB;
#pragma unroll
        for (int ks = 0; ks < 2; ++ks) {
            const uint32_t cb = (uint32_t)((ks * 16 + t2) * 2);
            uint32_t a_h[2][4], a_l[2][4];
#pragma unroll
            for (int mt = 0; mt < 2; ++mt) {
                uint32_t r0 = sb + (uint32_t)((warpM + mt * 16 + g) * 80) + cb;
                uint32_t r8 = r0 + 8 * 80;
                a_h[mt][0] = lds32(r0);        a_h[mt][1] = lds32(r8);
                a_h[mt][2] = lds32(r0 + 16);   a_h[mt][3] = lds32(r8 + 16);
                a_l[mt][0] = lds32(r0 + MATB); a_l[mt][1] = lds32(r8 + MATB);
                a_l[mt][2] = lds32(r0 + MATB + 16); a_l[mt][3] = lds32(r8 + MATB + 16);
            }
            uint32_t b_h[8][2], b_l[8][2];
#pragma unroll
            for (int nt = 0; nt < 8; ++nt) {
                uint32_t rr = sb + 2 * MATB + (uint32_t)((warpN + nt * 8 + g) * 80) + cb;
                b_h[nt][0] = lds32(rr);        b_h[nt][1] = lds32(rr + 16);
                b_l[nt][0] = lds32(rr + MATB); b_l[nt][1] = lds32(rr + MATB + 16);
            }
#pragma unroll
            for (int mt = 0; mt < 2; ++mt)
#pragma unroll
                for (int nt = 0; nt < 8; ++nt) {
                    mma16816(acc[mt][nt], a_h[mt], b_h[nt]);
                    mma16816(acc[mt][nt], a_h[mt], b_l[nt]);
                    mma16816(acc[mt][nt], a_l[mt], b_h[nt]);
                }
        }
        __syncthreads();
    }

#pragma unroll
    for (int mt = 0; mt < 2; ++mt) {
        int r0 = m0 + warpM + mt * 16 + g;
#pragma unroll
        for (int nt = 0; nt < 8; ++nt) {
            int cc = n0 + warpN + nt * 8 + t2;
            float b0 = bias[cc], b1 = bias[cc + 1];
            float v0 = acc[mt][nt][0] + b0, v1 = acc[mt][nt][1] + b1;
            float v2 = acc[mt][nt][2] + b0, v3 = acc[mt][nt][3] + b1;
            if (act == 0) {
                v0 = __fdividef(1.f, 1.f + __expf(-v0));
                v1 = __fdividef(1.f, 1.f + __expf(-v1));
                v2 = __fdividef(1.f, 1.f + __expf(-v2));
                v3 = __fdividef(1.f, 1.f + __expf(-v3));
            } else {
                v0 = tanhf(v0); v1 = tanhf(v1); v2 = tanhf(v2); v3 = tanhf(v3);
            }
            *reinterpret_cast<float2*>(&C[(size_t)r0 * 256 + cc])       = make_float2(v0, v1);
            *reinterpret_cast<float2*>(&C[(size_t)(r0 + 8) * 256 + cc]) = make_float2(v2, v3);
        }
    }
}

// =======================================================================================
// Scan (R4-proven): 256 threads/CTA, 25 packed slot-pairs, 4-deep cp.async score ring,
// depth-3 e/a register pipeline. Emits reads as bf16 hi/lo.
// =======================================================================================
__global__ void __launch_bounds__(256) scan_kernel(const float* __restrict__ S,
                                                   const float* __restrict__ E,
                                                   const float* __restrict__ A,
                                                   const float* __restrict__ M0,
                                                   __nv_bfloat16* __restrict__ Rhi,
                                                   __nv_bfloat16* __restrict__ Rlo)
{
    const int b = blockIdx.x;
    const int d = threadIdx.x;
    __shared__ __align__(16) float ring[4][52];

    u64 m[25];
#pragma unroll
    for (int j = 0; j < 25; ++j)
        m[j] = pack2(M0[(2 * j) * DV + d], M0[(2 * j + 1) * DV + d]);

    const float* sp = S + (size_t)b * LL * NN;
    const float* ep = E + (size_t)b * LL * DV + d;
    const float* ap = A + (size_t)b * LL * DV + d;
    __nv_bfloat16* rh = Rhi + (size_t)b * LL * DV + d;
    __nv_bfloat16* rl = Rlo + (size_t)b * LL * DV + d;

    if (d < NN) {
#pragma unroll
        for (int p = 0; p < 3; ++p) {
            cpasync4(smem_u32(&ring[p][d]), sp + (size_t)p * NN + d);
            asm volatile("cp.async.commit_group;" ::: "memory");
        }
        asm volatile("cp.async.wait_group 2;" ::: "memory");
    }
    float e0 = ep[0],      a0 = ap[0];
    float e1 = ep[DV],     a1 = ap[DV];
    float e2 = ep[2 * DV], a2 = ap[2 * DV];
    __syncthreads();

    for (int l = 0; l < LL; ++l) {
        const int n3 = (l + 3 < LL) ? (l + 3) : (LL - 1);
        if (d < NN) {
            cpasync4(smem_u32(&ring[(l + 3) & 3][d]), sp + (size_t)n3 * NN + d);
            asm volatile("cp.async.commit_group;" ::: "memory");
        }
        float en = ep[(size_t)n3 * DV];
        float an = ap[(size_t)n3 * DV];

        u64 apk  = pack2(a0, a0);
        u64 nepk = pack2(-e0, -e0);
        u64 r0 = 0ull, r1 = 0ull;
        const u64* sb = reinterpret_cast<const u64*>(ring[l & 3]);
#pragma unroll
        for (int j = 0; j < 25; ++j) {
            u64 spk = sb[j];
            if (j & 1) r1 = fma2(spk, m[j], r1);
            else       r0 = fma2(spk, m[j], r0);
            u64 tt = fma2(nepk, m[j], apk);
            m[j] = fma2(spk, tt, m[j]);
        }
        float2 rv = unpack2(add2(r0, r1));
        float rr = rv.x + rv.y;
        __nv_bfloat16 h  = __float2bfloat16(rr);
        __nv_bfloat16 lo = __float2bfloat16(rr - __bfloat162float(h));
        rh[(size_t)l * DV] = h;
        rl[(size_t)l * DV] = lo;

        if (d < NN) asm volatile("cp.async.wait_group 2;" ::: "memory");
        __syncthreads();
        e0 = e1; a0 = a1; e1 = e2; a1 = a2; e2 = en; a2 = an;
    }
}

// =======================================================================================
// Launch
// =======================================================================================
extern "C" void kernel_launch(void* const* d_in, const int* in_sizes, int n_in,
                              void* d_out, int out_size)
{
    const float* problems     = (const float*)d_in[0];
    const float* interactions = (const float*)d_in[1];
    const float* w_key        = (const float*)d_in[2];
    const float* w_erase_w    = (const float*)d_in[3];
    const float* w_erase_b    = (const float*)d_in[4];
    const float* w_add_w      = (const float*)d_in[5];
    const float* w_add_b      = (const float*)d_in[6];
    const float* w_out_w      = (const float*)d_in[7];
    const float* w_out_b      = (const float*)d_in[8];
    const float* init_memory  = (const float*)d_in[9];
    float* out = (float*)d_out;

    float *ge, *ga, *gs;
    __nv_bfloat16 *ibhi, *iblo, *pbhi, *pblo, *rhi, *rlo;
    __nv_bfloat16 *wehi, *welo, *wahi, *walo, *wohi, *wolo, *wkhi, *wklo;
    cudaGetSymbolAddress((void**)&ge,   g_e);
    cudaGetSymbolAddress((void**)&ga,   g_a);
    cudaGetSymbolAddress((void**)&gs,   g_score);
    cudaGetSymbolAddress((void**)&ibhi, g_ibhi);  cudaGetSymbolAddress((void**)&iblo, g_iblo);
    cudaGetSymbolAddress((void**)&pbhi, g_pbhi);  cudaGetSymbolAddress((void**)&pblo, g_pblo);
    cudaGetSymbolAddress((void**)&rhi,  g_rhi);   cudaGetSymbolAddress((void**)&rlo,  g_rlo);
    cudaGetSymbolAddress((void**)&wehi, g_wehi);  cudaGetSymbolAddress((void**)&welo, g_welo);
    cudaGetSymbolAddress((void**)&wahi, g_wahi);  cudaGetSymbolAddress((void**)&walo, g_walo);
    cudaGetSymbolAddress((void**)&wohi, g_wohi);  cudaGetSymbolAddress((void**)&wolo, g_wolo);
    cudaGetSymbolAddress((void**)&wkhi, g_wkhi);  cudaGetSymbolAddress((void**)&wklo, g_wklo);

    cudaFuncSetAttribute(gemm_hmma, cudaFuncAttributeMaxDynamicSharedMemorySize, 2 * BUFB);
    cudaFuncSetAttribute(score_hmma, cudaFuncAttributeMaxDynamicSharedMemorySize, 2 * SBUF);

    // conversions (f32 -> bf16 hi/lo)
    conv_kernel<<<(MM * DV / 4 + 255) / 256, 256>>>(interactions, ibhi, iblo, MM * DV / 4);
    conv_kernel<<<(MM * DK / 4 + 255) / 256, 256>>>(problems, pbhi, pblo, MM * DK / 4);
    conv_kernel<<<(DV * DV / 4 + 255) / 256, 256>>>(w_erase_w, wehi, welo, DV * DV / 4);
    conv_kernel<<<(DV * DV / 4 + 255) / 256, 256>>>(w_add_w, wahi, walo, DV * DV / 4);
    conv_kernel<<<(HH * (DV + DK) / 4 + 255) / 256, 256>>>(w_out_w, wohi, wolo, HH * (DV + DK) / 4);
    conv_kernel<<<(NN * DK / 4 + 255) / 256, 256>>>(w_key, wkhi, wklo, NN * DK / 4);  // rows 50..63 stay 0

    // attention scores (HMMA + softmax epilogue)
    score_hmma<<<MM / 128, 128, 2 * SBUF>>>(pbhi, pblo, wkhi, wklo, gs);

    // gate GEMMs (HMMA)
    dim3 gg(MM / 128, 2);
    gemm_hmma<<<gg, 256, 2 * BUFB>>>(ibhi, iblo, DV, DV, ibhi, iblo, DV,
                                     wehi, welo, DV, w_erase_b, ge, /*sigmoid*/0);
    gemm_hmma<<<gg, 256, 2 * BUFB>>>(ibhi, iblo, DV, DV, ibhi, iblo, DV,
                                     wahi, walo, DV, w_add_b, ga, /*tanh*/1);

    // sequential memory scan
    scan_kernel<<<BB, 256>>>(gs, ge, ga, init_memory, rhi, rlo);

    // output GEMM: A = [reads(256) | problems(128)], K = 384
    gemm_hmma<<<gg, 256, 2 * BUFB>>>(rhi, rlo, DV, DV, pbhi, pblo, DK,
                                     wohi, wolo, DV + DK, w_out_b, out, /*tanh*/1);
}

// round 7
// speedup vs baseline: 1.3936x; 1.2285x over previous
#include <cuda_runtime.h>
#include <cuda_bf16.h>
#include <math.h>
#include <stdint.h>

#define BB   128
#define LL   1024
#define DK   128
#define DV   256
#define HH   256
#define NN   50
#define MM   (BB * LL)   // 131072 rows

typedef unsigned long long u64;

// ---------------- packed f32x2 helpers ----------------
__device__ __forceinline__ u64 fma2(u64 a, u64 b, u64 c) {
    u64 d; asm("fma.rn.f32x2 %0, %1, %2, %3;" : "=l"(d) : "l"(a), "l"(b), "l"(c)); return d;
}
__device__ __forceinline__ u64 add2(u64 a, u64 b) {
    u64 d; asm("add.rn.f32x2 %0, %1, %2;" : "=l"(d) : "l"(a), "l"(b)); return d;
}
__device__ __forceinline__ u64 pack2(float lo, float hi) {
    u64 r; asm("mov.b64 %0, {%1, %2};" : "=l"(r) : "f"(lo), "f"(hi)); return r;
}
__device__ __forceinline__ float2 unpack2(u64 v) {
    float2 r; asm("mov.b64 {%0, %1}, %2;" : "=f"(r.x), "=f"(r.y) : "l"(v)); return r;
}

// ---------------- async / smem helpers ----------------
__device__ __forceinline__ uint32_t smem_u32(const void* p) {
    uint32_t a;
    asm("{ .reg .u64 t; cvta.to.shared.u64 t, %1; cvt.u32.u64 %0, t; }" : "=r"(a) : "l"(p));
    return a;
}
__device__ __forceinline__ void cpasync16(uint32_t saddr, const void* gptr) {
    asm volatile("cp.async.cg.shared.global [%0], [%1], 16;" :: "r"(saddr), "l"(gptr) : "memory");
}
__device__ __forceinline__ void cpasync4(uint32_t saddr, const void* gptr) {
    asm volatile("cp.async.ca.shared.global [%0], [%1], 4;" :: "r"(saddr), "l"(gptr) : "memory");
}
__device__ __forceinline__ uint32_t lds32(uint32_t addr) {
    uint32_t v; asm volatile("ld.shared.b32 %0, [%1];" : "=r"(v) : "r"(addr)); return v;
}
__device__ __forceinline__ void mma16816(float* c, const uint32_t* a, const uint32_t* b) {
    asm volatile(
        "mma.sync.aligned.m16n8k16.row.col.f32.bf16.bf16.f32 "
        "{%0,%1,%2,%3}, {%4,%5,%6,%7}, {%8,%9}, {%0,%1,%2,%3};"
        : "+f"(c[0]), "+f"(c[1]), "+f"(c[2]), "+f"(c[3])
        : "r"(a[0]), "r"(a[1]), "r"(a[2]), "r"(a[3]), "r"(b[0]), "r"(b[1]));
}

// ------------------------- scratch (device globals; no allocs) -------------------------
__device__ float          g_e[(size_t)MM * DV];
__device__ float          g_a[(size_t)MM * DV];
__device__ float          g_score[(size_t)MM * NN];
__device__ __nv_bfloat16  g_ibhi[(size_t)MM * DV], g_iblo[(size_t)MM * DV];   // interactions
__device__ __nv_bfloat16  g_pbhi[(size_t)MM * DK], g_pblo[(size_t)MM * DK];   // problems
__device__ __nv_bfloat16  g_rhi[(size_t)MM * DV],  g_rlo[(size_t)MM * DV];    // scan reads
__device__ __nv_bfloat16  g_wehi[DV * DV], g_welo[DV * DV];
__device__ __nv_bfloat16  g_wahi[DV * DV], g_walo[DV * DV];
__device__ __nv_bfloat16  g_wohi[HH * (DV + DK)], g_wolo[HH * (DV + DK)];
__device__ __nv_bfloat16  g_wkhi[64 * DK], g_wklo[64 * DK];   // w_key padded to 64 rows (rest stays 0)

// =======================================================================================
// f32 -> bf16 hi/lo split conversion (vectorized by 4)
// =======================================================================================
__global__ void __launch_bounds__(256) conv_kernel(const float* __restrict__ x,
                                                   __nv_bfloat16* __restrict__ hi,
                                                   __nv_bfloat16* __restrict__ lo,
                                                   int n4)
{
    int i = blockIdx.x * 256 + threadIdx.x;
    if (i >= n4) return;
    float4 v = reinterpret_cast<const float4*>(x)[i];
    ushort4 h, l;
    __nv_bfloat16 b; float f;
    b = __float2bfloat16(v.x); h.x = __bfloat16_as_ushort(b); f = v.x - __bfloat162float(b);
    l.x = __bfloat16_as_ushort(__float2bfloat16(f));
    b = __float2bfloat16(v.y); h.y = __bfloat16_as_ushort(b); f = v.y - __bfloat162float(b);
    l.y = __bfloat16_as_ushort(__float2bfloat16(f));
    b = __float2bfloat16(v.z); h.z = __bfloat16_as_ushort(b); f = v.z - __bfloat162float(b);
    l.z = __bfloat16_as_ushort(__float2bfloat16(f));
    b = __float2bfloat16(v.w); h.w = __bfloat16_as_ushort(b); f = v.w - __bfloat162float(b);
    l.w = __bfloat16_as_ushort(__float2bfloat16(f));
    reinterpret_cast<ushort4*>(hi)[i] = h;
    reinterpret_cast<ushort4*>(lo)[i] = l;
}

// =======================================================================================
// HMMA score GEMM + softmax epilogue (R6-proven).
// =======================================================================================
#define SMATA 10240u
#define SMATB 5120u
#define SBUF  30720u

__global__ void __launch_bounds__(128)
score_hmma(const __nv_bfloat16* __restrict__ phi, const __nv_bfloat16* __restrict__ plo,
           const __nv_bfloat16* __restrict__ wkhi, const __nv_bfloat16* __restrict__ wklo,
           float* __restrict__ S)
{
    extern __shared__ __align__(16) char dsm[];
    const uint32_t dbase = smem_u32(dsm);

    const int tid = threadIdx.x;
    const int m0 = blockIdx.x * 128;
    const int wid = tid >> 5;
    const int lane = tid & 31;
    const int g  = lane >> 2;
    const int t2 = (lane & 3) * 2;
    const int warpM = wid * 32;

    auto load_chunk = [&](int c) {
        uint32_t sb = dbase + (uint32_t)(c & 1) * SBUF;
        int k0 = c * 32;
#pragma unroll
        for (int i = 0; i < 4; ++i) {
            int idx = tid + 128 * i;
            int row = idx >> 2, seg = idx & 3;
            uint32_t so = (uint32_t)(row * 80 + seg * 16);
            size_t gA = (size_t)(m0 + row) * DK + k0 + seg * 8;
            cpasync16(sb + so,         phi + gA);
            cpasync16(sb + SMATA + so, plo + gA);
        }
#pragma unroll
        for (int i = 0; i < 2; ++i) {
            int idx = tid + 128 * i;
            int row = idx >> 2, seg = idx & 3;
            uint32_t so = (uint32_t)(row * 80 + seg * 16);
            size_t gB = (size_t)row * DK + k0 + seg * 8;
            cpasync16(sb + 2 * SMATA + so,         wkhi + gB);
            cpasync16(sb + 2 * SMATA + SMATB + so, wklo + gB);
        }
        asm volatile("cp.async.commit_group;" ::: "memory");
    };

    float acc[2][8][4];
#pragma unroll
    for (int mt = 0; mt < 2; ++mt)
#pragma unroll
        for (int nt = 0; nt < 8; ++nt)
#pragma unroll
            for (int q = 0; q < 4; ++q) acc[mt][nt][q] = 0.f;

    load_chunk(0);

    for (int c = 0; c < 4; ++c) {
        if (c + 1 < 4) {
            load_chunk(c + 1);
            asm volatile("cp.async.wait_group 1;" ::: "memory");
        } else {
            asm volatile("cp.async.wait_group 0;" ::: "memory");
        }
        __syncthreads();

        uint32_t sb = dbase + (uint32_t)(c & 1) * SBUF;
#pragma unroll
        for (int ks = 0; ks < 2; ++ks) {
            const uint32_t cb = (uint32_t)((ks * 16 + t2) * 2);
            uint32_t a_h[2][4], a_l[2][4];
#pragma unroll
            for (int mt = 0; mt < 2; ++mt) {
                uint32_t r0 = sb + (uint32_t)((warpM + mt * 16 + g) * 80) + cb;
                uint32_t r8 = r0 + 8 * 80;
                a_h[mt][0] = lds32(r0);         a_h[mt][1] = lds32(r8);
                a_h[mt][2] = lds32(r0 + 16);    a_h[mt][3] = lds32(r8 + 16);
                a_l[mt][0] = lds32(r0 + SMATA); a_l[mt][1] = lds32(r8 + SMATA);
                a_l[mt][2] = lds32(r0 + SMATA + 16); a_l[mt][3] = lds32(r8 + SMATA + 16);
            }
            uint32_t b_h[8][2], b_l[8][2];
#pragma unroll
            for (int nt = 0; nt < 8; ++nt) {
                uint32_t rr = sb + 2 * SMATA + (uint32_t)((nt * 8 + g) * 80) + cb;
                b_h[nt][0] = lds32(rr);          b_h[nt][1] = lds32(rr + 16);
                b_l[nt][0] = lds32(rr + SMATB);  b_l[nt][1] = lds32(rr + SMATB + 16);
            }
#pragma unroll
            for (int mt = 0; mt < 2; ++mt)
#pragma unroll
                for (int nt = 0; nt < 8; ++nt) {
                    mma16816(acc[mt][nt], a_h[mt], b_h[nt]);
                    mma16816(acc[mt][nt], a_h[mt], b_l[nt]);
                    mma16816(acc[mt][nt], a_l[mt], b_h[nt]);
                }
        }
        __syncthreads();
    }

#pragma unroll
    for (int mt = 0; mt < 2; ++mt) {
#pragma unroll
        for (int hf = 0; hf < 2; ++hf) {
            int row = m0 + warpM + mt * 16 + g + hf * 8;
            float v[16];
#pragma unroll
            for (int nt = 0; nt < 8; ++nt) {
                int c0 = nt * 8 + t2;
                v[2 * nt]     = (c0     < NN) ? acc[mt][nt][2 * hf]     : -1e30f;
                v[2 * nt + 1] = (c0 + 1 < NN) ? acc[mt][nt][2 * hf + 1] : -1e30f;
            }
            float mx = v[0];
#pragma unroll
            for (int q = 1; q < 16; ++q) mx = fmaxf(mx, v[q]);
            mx = fmaxf(mx, __shfl_xor_sync(0xffffffffu, mx, 1));
            mx = fmaxf(mx, __shfl_xor_sync(0xffffffffu, mx, 2));
            float sum = 0.f;
#pragma unroll
            for (int q = 0; q < 16; ++q) { v[q] = __expf(v[q] - mx); sum += v[q]; }
            sum += __shfl_xor_sync(0xffffffffu, sum, 1);
            sum += __shfl_xor_sync(0xffffffffu, sum, 2);
            float inv = __fdividef(1.f, sum);
            float* op = S + (size_t)row * NN;
#pragma unroll
            for (int nt = 0; nt < 8; ++nt) {
                int c0 = nt * 8 + t2;
                if (c0 < NN)
                    *reinterpret_cast<float2*>(op + c0) =
                        make_float2(v[2 * nt] * inv, v[2 * nt + 1] * inv);
            }
        }
    }
}

// =======================================================================================
// HMMA bf16 hi/lo 3-pass GEMM, dual-target (R6 core loop, R5 grid-sharing idea):
// grid.x = n-blocks over both targets (fast-varying => A L2-reuse across targets),
// grid.y = m-blocks. n-blocks [0,nsplit) -> target0, rest -> target1.
// =======================================================================================
#define MATB 10240u
#define BUFB 40960u

__global__ void __launch_bounds__(256)
gemm_hmma(const __nv_bfloat16* __restrict__ a1hi, const __nv_bfloat16* __restrict__ a1lo,
          int lda1, int k1len,
          const __nv_bfloat16* __restrict__ a2hi, const __nv_bfloat16* __restrict__ a2lo,
          int lda2, int K,
          const __nv_bfloat16* __restrict__ w0hi, const __nv_bfloat16* __restrict__ w0lo,
          const float* __restrict__ b0, float* __restrict__ C0, int act0,
          const __nv_bfloat16* __restrict__ w1hi, const __nv_bfloat16* __restrict__ w1lo,
          const float* __restrict__ b1, float* __restrict__ C1, int act1,
          int nsplit)
{
    extern __shared__ __align__(16) char dsm[];
    const uint32_t dbase = smem_u32(dsm);

    const int tid = threadIdx.x;
    const int m0 = blockIdx.y * 128;
    const int nb = blockIdx.x;

    const __nv_bfloat16 *whi, *wlo; const float* bias; float* C; int act, nloc;
    if (nb < nsplit) { whi = w0hi; wlo = w0lo; bias = b0; C = C0; act = act0; nloc = nb * 128; }
    else             { whi = w1hi; wlo = w1lo; bias = b1; C = C1; act = act1; nloc = (nb - nsplit) * 128; }

    const int wid = tid >> 5;
    const int lane = tid & 31;
    const int g  = lane >> 2;
    const int t2 = (lane & 3) * 2;
    const int warpM = (wid & 3) * 32;
    const int warpN = (wid >> 2) * 64;

    const int nch = K / 32;

    auto load_chunk = [&](int c) {
        uint32_t sb = dbase + (uint32_t)(c & 1) * BUFB;
        int k0 = c * 32;
        const __nv_bfloat16 *shi, *slo; int ld, kk;
        if (k0 < k1len) { shi = a1hi; slo = a1lo; ld = lda1; kk = k0; }
        else            { shi = a2hi; slo = a2lo; ld = lda2; kk = k0 - k1len; }
#pragma unroll
        for (int i = 0; i < 2; ++i) {
            int gidx = tid + 256 * i;
            int row = gidx >> 2, seg = gidx & 3;
            uint32_t so = (uint32_t)(row * 80 + seg * 16);
            size_t gA = (size_t)(m0 + row) * ld + kk + seg * 8;
            cpasync16(sb + so,            shi + gA);
            cpasync16(sb + MATB + so,     slo + gA);
            size_t gB = (size_t)(nloc + row) * K + k0 + seg * 8;
            cpasync16(sb + 2 * MATB + so, whi + gB);
            cpasync16(sb + 3 * MATB + so, wlo + gB);
        }
        asm volatile("cp.async.commit_group;" ::: "memory");
    };

    float acc[2][8][4];
#pragma unroll
    for (int mt = 0; mt < 2; ++mt)
#pragma unroll
        for (int nt = 0; nt < 8; ++nt)
#pragma unroll
            for (int q = 0; q < 4; ++q) acc[mt][nt][q] = 0.f;

    load_chunk(0);

    for (int c = 0; c < nch; ++c) {
        if (c + 1 < nch) {
            load_chunk(c + 1);
            asm volatile("cp.async.wait_group 1;" ::: "memory");
        } else {
            asm volatile("cp.async.wait_group 0;" ::: "memory");
        }
        __syncthreads();

        uint32_t sb = dbase + (uint32_t)(c & 1) * BUFB;
#pragma unroll
        for (int ks = 0; ks < 2; ++ks) {
            const uint32_t cb = (uint32_t)((ks * 16 + t2) * 2);
            uint32_t a_h[2][4], a_l[2][4];
#pragma unroll
            for (int mt = 0; mt < 2; ++mt) {
                uint32_t r0 = sb + (uint32_t)((warpM + mt * 16 + g) * 80) + cb;
                uint32_t r8 = r0 + 8 * 80;
                a_h[mt][0] = lds32(r0);        a_h[mt][1] = lds32(r8);
                a_h[mt][2] = lds32(r0 + 16);   a_h[mt][3] = lds32(r8 + 16);
                a_l[mt][0] = lds32(r0 + MATB); a_l[mt][1] = lds32(r8 + MATB);
                a_l[mt][2] = lds32(r0 + MATB + 16); a_l[mt][3] = lds32(r8 + MATB + 16);
            }
            uint32_t b_h[8][2], b_l[8][2];
#pragma unroll
            for (int nt = 0; nt < 8; ++nt) {
                uint32_t rr = sb + 2 * MATB + (uint32_t)((warpN + nt * 8 + g) * 80) + cb;
                b_h[nt][0] = lds32(rr);        b_h[nt][1] = lds32(rr + 16);
                b_l[nt][0] = lds32(rr + MATB); b_l[nt][1] = lds32(rr + MATB + 16);
            }
#pragma unroll
            for (int mt = 0; mt < 2; ++mt)
#pragma unroll
                for (int nt = 0; nt < 8; ++nt) {
                    mma16816(acc[mt][nt], a_h[mt], b_h[nt]);
                    mma16816(acc[mt][nt], a_h[mt], b_l[nt]);
                    mma16816(acc[mt][nt], a_l[mt], b_h[nt]);
                }
        }
        __syncthreads();
    }

#pragma unroll
    for (int mt = 0; mt < 2; ++mt) {
        int r0 = m0 + warpM + mt * 16 + g;
#pragma unroll
        for (int nt = 0; nt < 8; ++nt) {
            int cc = nloc + warpN + nt * 8 + t2;
            float bb0 = bias[cc], bb1 = bias[cc + 1];
            float v0 = acc[mt][nt][0] + bb0, v1 = acc[mt][nt][1] + bb1;
            float v2 = acc[mt][nt][2] + bb0, v3 = acc[mt][nt][3] + bb1;
            if (act == 0) {
                v0 = __fdividef(1.f, 1.f + __expf(-v0));
                v1 = __fdividef(1.f, 1.f + __expf(-v1));
                v2 = __fdividef(1.f, 1.f + __expf(-v2));
                v3 = __fdividef(1.f, 1.f + __expf(-v3));
            } else {
                v0 = tanhf(v0); v1 = tanhf(v1); v2 = tanhf(v2); v3 = tanhf(v3);
            }
            *reinterpret_cast<float2*>(&C[(size_t)r0 * 256 + cc])       = make_float2(v0, v1);
            *reinterpret_cast<float2*>(&C[(size_t)(r0 + 8) * 256 + cc]) = make_float2(v2, v3);
        }
    }
}

// =======================================================================================
// Scan: groups of 4 steps per barrier. 16-deep score ring (prefetch distance 8 steps),
// e/a 3-buffer register pipeline. One commit/wait/barrier per 4 steps.
// =======================================================================================
__global__ void __launch_bounds__(256) scan_kernel(const float* __restrict__ S,
                                                   const float* __restrict__ E,
                                                   const float* __restrict__ A,
                                                   const float* __restrict__ M0,
                                                   __nv_bfloat16* __restrict__ Rhi,
                                                   __nv_bfloat16* __restrict__ Rlo)
{
    const int b = blockIdx.x;
    const int d = threadIdx.x;
    __shared__ __align__(16) float ring[16][52];

    u64 m[25];
#pragma unroll
    for (int j = 0; j < 25; ++j)
        m[j] = pack2(M0[(2 * j) * DV + d], M0[(2 * j + 1) * DV + d]);

    const float* sp = S + (size_t)b * LL * NN;
    const float* ep = E + (size_t)b * LL * DV + d;
    const float* ap = A + (size_t)b * LL * DV + d;
    __nv_bfloat16* rh = Rhi + (size_t)b * LL * DV + d;
    __nv_bfloat16* rl = Rlo + (size_t)b * LL * DV + d;

    // preload score groups 0 and 1 (steps 0..7)
    if (d < NN) {
#pragma unroll
        for (int st = 0; st < 4; ++st)
            cpasync4(smem_u32(&ring[st][d]), sp + (size_t)st * NN + d);
        asm volatile("cp.async.commit_group;" ::: "memory");
#pragma unroll
        for (int st = 0; st < 4; ++st)
            cpasync4(smem_u32(&ring[4 + st][d]), sp + (size_t)(4 + st) * NN + d);
        asm volatile("cp.async.commit_group;" ::: "memory");
        asm volatile("cp.async.wait_group 1;" ::: "memory");
    }
    float ecur[4], acur[4], enx[4], anx[4];
#pragma unroll
    for (int st = 0; st < 4; ++st) { ecur[st] = ep[(size_t)st * DV]; acur[st] = ap[(size_t)st * DV]; }
#pragma unroll
    for (int st = 0; st < 4; ++st) { enx[st] = ep[(size_t)(4 + st) * DV]; anx[st] = ap[(size_t)(4 + st) * DV]; }
    __syncthreads();

    for (int gi = 0; gi < LL / 4; ++gi) {
        const int base = gi * 4;
        // prefetch scores for group gi+2 (slots (base+8..+11) & 15 — disjoint from read set)
        if (d < NN) {
#pragma unroll
            for (int st = 0; st < 4; ++st) {
                int ll = base + 8 + st; if (ll > LL - 1) ll = LL - 1;
                cpasync4(smem_u32(&ring[(base + 8 + st) & 15][d]), sp + (size_t)ll * NN + d);
            }
            asm volatile("cp.async.commit_group;" ::: "memory");
        }
        // prefetch e/a for group gi+2
        float etmp[4], atmp[4];
#pragma unroll
        for (int st = 0; st < 4; ++st) {
            int ll = base + 8 + st; if (ll > LL - 1) ll = LL - 1;
            etmp[st] = ep[(size_t)ll * DV];
            atmp[st] = ap[(size_t)ll * DV];
        }

        // process 4 steps back-to-back (no barrier between)
#pragma unroll
        for (int st = 0; st < 4; ++st) {
            const int l = base + st;
            u64 apk  = pack2(acur[st], acur[st]);
            u64 nepk = pack2(-ecur[st], -ecur[st]);
            u64 r0 = 0ull, r1 = 0ull;
            const u64* sb = reinterpret_cast<const u64*>(ring[l & 15]);
#pragma unroll
            for (int j = 0; j < 25; ++j) {
                u64 spk = sb[j];
                if (j & 1) r1 = fma2(spk, m[j], r1);
                else       r0 = fma2(spk, m[j], r0);
                u64 tt = fma2(nepk, m[j], apk);
                m[j] = fma2(spk, tt, m[j]);
            }
            float2 rv = unpack2(add2(r0, r1));
            float rr = rv.x + rv.y;
            __nv_bfloat16 h  = __float2bfloat16(rr);
            __nv_bfloat16 lo = __float2bfloat16(rr - __bfloat162float(h));
            rh[(size_t)l * DV] = h;
            rl[(size_t)l * DV] = lo;
        }

        if (d < NN) asm volatile("cp.async.wait_group 1;" ::: "memory");
        __syncthreads();
#pragma unroll
        for (int st = 0; st < 4; ++st) {
            ecur[st] = enx[st]; acur[st] = anx[st];
            enx[st] = etmp[st]; anx[st] = atmp[st];
        }
    }
}

// =======================================================================================
// Launch
// =======================================================================================
extern "C" void kernel_launch(void* const* d_in, const int* in_sizes, int n_in,
                              void* d_out, int out_size)
{
    const float* problems     = (const float*)d_in[0];
    const float* interactions = (const float*)d_in[1];
    const float* w_key        = (const float*)d_in[2];
    const float* w_erase_w    = (const float*)d_in[3];
    const float* w_erase_b    = (const float*)d_in[4];
    const float* w_add_w      = (const float*)d_in[5];
    const float* w_add_b      = (const float*)d_in[6];
    const float* w_out_w      = (const float*)d_in[7];
    const float* w_out_b      = (const float*)d_in[8];
    const float* init_memory  = (const float*)d_in[9];
    float* out = (float*)d_out;

    float *ge, *ga, *gs;
    __nv_bfloat16 *ibhi, *iblo, *pbhi, *pblo, *rhi, *rlo;
    __nv_bfloat16 *wehi, *welo, *wahi, *walo, *wohi, *wolo, *wkhi, *wklo;
    cudaGetSymbolAddress((void**)&ge,   g_e);
    cudaGetSymbolAddress((void**)&ga,   g_a);
    cudaGetSymbolAddress((void**)&gs,   g_score);
    cudaGetSymbolAddress((void**)&ibhi, g_ibhi);  cudaGetSymbolAddress((void**)&iblo, g_iblo);
    cudaGetSymbolAddress((void**)&pbhi, g_pbhi);  cudaGetSymbolAddress((void**)&pblo, g_pblo);
    cudaGetSymbolAddress((void**)&rhi,  g_rhi);   cudaGetSymbolAddress((void**)&rlo,  g_rlo);
    cudaGetSymbolAddress((void**)&wehi, g_wehi);  cudaGetSymbolAddress((void**)&welo, g_welo);
    cudaGetSymbolAddress((void**)&wahi, g_wahi);  cudaGetSymbolAddress((void**)&walo, g_walo);
    cudaGetSymbolAddress((void**)&wohi, g_wohi);  cudaGetSymbolAddress((void**)&wolo, g_wolo);
    cudaGetSymbolAddress((void**)&wkhi, g_wkhi);  cudaGetSymbolAddress((void**)&wklo, g_wklo);

    cudaFuncSetAttribute(gemm_hmma, cudaFuncAttributeMaxDynamicSharedMemorySize, 2 * BUFB);
    cudaFuncSetAttribute(score_hmma, cudaFuncAttributeMaxDynamicSharedMemorySize, 2 * SBUF);

    // conversions (f32 -> bf16 hi/lo)
    conv_kernel<<<(MM * DV / 4 + 255) / 256, 256>>>(interactions, ibhi, iblo, MM * DV / 4);
    conv_kernel<<<(MM * DK / 4 + 255) / 256, 256>>>(problems, pbhi, pblo, MM * DK / 4);
    conv_kernel<<<(DV * DV / 4 + 255) / 256, 256>>>(w_erase_w, wehi, welo, DV * DV / 4);
    conv_kernel<<<(DV * DV / 4 + 255) / 256, 256>>>(w_add_w, wahi, walo, DV * DV / 4);
    conv_kernel<<<(HH * (DV + DK) / 4 + 255) / 256, 256>>>(w_out_w, wohi, wolo, HH * (DV + DK) / 4);
    conv_kernel<<<(NN * DK / 4 + 255) / 256, 256>>>(w_key, wkhi, wklo, NN * DK / 4);

    // attention scores (HMMA + softmax epilogue)
    score_hmma<<<MM / 128, 128, 2 * SBUF>>>(pbhi, pblo, wkhi, wklo, gs);

    // merged gate GEMMs: n-targets {e:0,1, a:2,3} share each A m-block through L2
    dim3 gg(4, MM / 128);
    gemm_hmma<<<gg, 256, 2 * BUFB>>>(ibhi, iblo, DV, DV, ibhi, iblo, DV, DV,
                                     wehi, welo, w_erase_b, ge, /*sigmoid*/0,
                                     wahi, walo, w_add_b,   ga, /*tanh*/1, 2);

    // sequential memory scan
    scan_kernel<<<BB, 256>>>(gs, ge, ga, init_memory, rhi, rlo);

    // output GEMM: A = [reads(256) | problems(128)], K = 384; n-blocks fast for A reuse
    dim3 go(2, MM / 128);
    gemm_hmma<<<go, 256, 2 * BUFB>>>(rhi, rlo, DV, DV, pbhi, pblo, DK, DV + DK,
                                     wohi, wolo, w_out_b, out, /*tanh*/1,
                                     wohi, wolo, w_out_b, out, 1, 2);
}

// round 8
// speedup vs baseline: 1.5355x; 1.1018x over previous
#include <cuda_runtime.h>
#include <cuda_bf16.h>
#include <math.h>
#include <stdint.h>

#define BB   128
#define LL   1024
#define DK   128
#define DV   256
#define HH   256
#define NN   50
#define MM   (BB * LL)   // 131072 rows

typedef unsigned long long u64;

// ---------------- packed f32x2 helpers ----------------
__device__ __forceinline__ u64 fma2(u64 a, u64 b, u64 c) {
    u64 d; asm("fma.rn.f32x2 %0, %1, %2, %3;" : "=l"(d) : "l"(a), "l"(b), "l"(c)); return d;
}
__device__ __forceinline__ u64 add2(u64 a, u64 b) {
    u64 d; asm("add.rn.f32x2 %0, %1, %2;" : "=l"(d) : "l"(a), "l"(b)); return d;
}
__device__ __forceinline__ u64 pack2(float lo, float hi) {
    u64 r; asm("mov.b64 %0, {%1, %2};" : "=l"(r) : "f"(lo), "f"(hi)); return r;
}
__device__ __forceinline__ float2 unpack2(u64 v) {
    float2 r; asm("mov.b64 {%0, %1}, %2;" : "=f"(r.x), "=f"(r.y) : "l"(v)); return r;
}

// ---------------- async / smem helpers ----------------
__device__ __forceinline__ uint32_t smem_u32(const void* p) {
    uint32_t a;
    asm("{ .reg .u64 t; cvta.to.shared.u64 t, %1; cvt.u32.u64 %0, t; }" : "=r"(a) : "l"(p));
    return a;
}
__device__ __forceinline__ void cpasync16(uint32_t saddr, const void* gptr) {
    asm volatile("cp.async.cg.shared.global [%0], [%1], 16;" :: "r"(saddr), "l"(gptr) : "memory");
}
__device__ __forceinline__ void cpasync8(uint32_t saddr, const void* gptr) {
    asm volatile("cp.async.ca.shared.global [%0], [%1], 8;" :: "r"(saddr), "l"(gptr) : "memory");
}
__device__ __forceinline__ uint32_t lds32(uint32_t addr) {
    uint32_t v; asm volatile("ld.shared.b32 %0, [%1];" : "=r"(v) : "r"(addr)); return v;
}
__device__ __forceinline__ void mma16816(float* c, const uint32_t* a, const uint32_t* b) {
    asm volatile(
        "mma.sync.aligned.m16n8k16.row.col.f32.bf16.bf16.f32 "
        "{%0,%1,%2,%3}, {%4,%5,%6,%7}, {%8,%9}, {%0,%1,%2,%3};"
        : "+f"(c[0]), "+f"(c[1]), "+f"(c[2]), "+f"(c[3])
        : "r"(a[0]), "r"(a[1]), "r"(a[2]), "r"(a[3]), "r"(b[0]), "r"(b[1]));
}

// ------------------------- scratch (device globals; no allocs) -------------------------
__device__ float          g_e[(size_t)MM * DV];
__device__ float          g_a[(size_t)MM * DV];
__device__ float          g_score[(size_t)MM * NN];
__device__ __nv_bfloat16  g_ibhi[(size_t)MM * DV], g_iblo[(size_t)MM * DV];   // interactions
__device__ __nv_bfloat16  g_pbhi[(size_t)MM * DK], g_pblo[(size_t)MM * DK];   // problems
__device__ __nv_bfloat16  g_rhi[(size_t)MM * DV],  g_rlo[(size_t)MM * DV];    // scan reads
__device__ __nv_bfloat16  g_wehi[DV * DV], g_welo[DV * DV];
__device__ __nv_bfloat16  g_wahi[DV * DV], g_walo[DV * DV];
__device__ __nv_bfloat16  g_wohi[HH * (DV + DK)], g_wolo[HH * (DV + DK)];
__device__ __nv_bfloat16  g_wkhi[64 * DK], g_wklo[64 * DK];   // w_key padded to 64 rows (rest stays 0)

// =======================================================================================
// f32 -> bf16 hi/lo split conversion (vectorized by 4)
// =======================================================================================
__device__ __forceinline__ void split4(float4 v, ushort4& h, ushort4& l) {
    __nv_bfloat16 b; float f;
    b = __float2bfloat16(v.x); h.x = __bfloat16_as_ushort(b); f = v.x - __bfloat162float(b);
    l.x = __bfloat16_as_ushort(__float2bfloat16(f));
    b = __float2bfloat16(v.y); h.y = __bfloat16_as_ushort(b); f = v.y - __bfloat162float(b);
    l.y = __bfloat16_as_ushort(__float2bfloat16(f));
    b = __float2bfloat16(v.z); h.z = __bfloat16_as_ushort(b); f = v.z - __bfloat162float(b);
    l.z = __bfloat16_as_ushort(__float2bfloat16(f));
    b = __float2bfloat16(v.w); h.w = __bfloat16_as_ushort(b); f = v.w - __bfloat162float(b);
    l.w = __bfloat16_as_ushort(__float2bfloat16(f));
}

__global__ void __launch_bounds__(256) conv_kernel(const float* __restrict__ x,
                                                   __nv_bfloat16* __restrict__ hi,
                                                   __nv_bfloat16* __restrict__ lo,
                                                   int n4)
{
    int i = blockIdx.x * 256 + threadIdx.x;
    if (i >= n4) return;
    ushort4 h, l;
    split4(reinterpret_cast<const float4*>(x)[i], h, l);
    reinterpret_cast<ushort4*>(hi)[i] = h;
    reinterpret_cast<ushort4*>(lo)[i] = l;
}

// All four weight matrices in one launch (grid-stride over 4 segments)
__global__ void __launch_bounds__(256) conv_w_kernel(
    const float* __restrict__ x0, __nv_bfloat16* __restrict__ h0, __nv_bfloat16* __restrict__ l0, int n0,
    const float* __restrict__ x1, __nv_bfloat16* __restrict__ h1, __nv_bfloat16* __restrict__ l1, int n1,
    const float* __restrict__ x2, __nv_bfloat16* __restrict__ h2, __nv_bfloat16* __restrict__ l2, int n2,
    const float* __restrict__ x3, __nv_bfloat16* __restrict__ h3, __nv_bfloat16* __restrict__ l3, int n3)
{
    int i = blockIdx.x * 256 + threadIdx.x;
    const float* x; __nv_bfloat16 *hi, *lo; int j = i;
    if      (j < n0)                { x = x0; hi = h0; lo = l0; }
    else if ((j -= n0) < n1)        { x = x1; hi = h1; lo = l1; }
    else if ((j -= n1) < n2)        { x = x2; hi = h2; lo = l2; }
    else if ((j -= n2) < n3)        { x = x3; hi = h3; lo = l3; }
    else return;
    ushort4 h, l;
    split4(reinterpret_cast<const float4*>(x)[j], h, l);
    reinterpret_cast<ushort4*>(hi)[j] = h;
    reinterpret_cast<ushort4*>(lo)[j] = l;
}

// =======================================================================================
// HMMA score GEMM + softmax epilogue (R6-proven).
// =======================================================================================
#define SMATA 10240u
#define SMATB 5120u
#define SBUF  30720u

__global__ void __launch_bounds__(128)
score_hmma(const __nv_bfloat16* __restrict__ phi, const __nv_bfloat16* __restrict__ plo,
           const __nv_bfloat16* __restrict__ wkhi, const __nv_bfloat16* __restrict__ wklo,
           float* __restrict__ S)
{
    extern __shared__ __align__(16) char dsm[];
    const uint32_t dbase = smem_u32(dsm);

    const int tid = threadIdx.x;
    const int m0 = blockIdx.x * 128;
    const int wid = tid >> 5;
    const int lane = tid & 31;
    const int g  = lane >> 2;
    const int t2 = (lane & 3) * 2;
    const int warpM = wid * 32;

    auto load_chunk = [&](int c) {
        uint32_t sb = dbase + (uint32_t)(c & 1) * SBUF;
        int k0 = c * 32;
#pragma unroll
        for (int i = 0; i < 4; ++i) {
            int idx = tid + 128 * i;
            int row = idx >> 2, seg = idx & 3;
            uint32_t so = (uint32_t)(row * 80 + seg * 16);
            size_t gA = (size_t)(m0 + row) * DK + k0 + seg * 8;
            cpasync16(sb + so,         phi + gA);
            cpasync16(sb + SMATA + so, plo + gA);
        }
#pragma unroll
        for (int i = 0; i < 2; ++i) {
            int idx = tid + 128 * i;
            int row = idx >> 2, seg = idx & 3;
            uint32_t so = (uint32_t)(row * 80 + seg * 16);
            size_t gB = (size_t)row * DK + k0 + seg * 8;
            cpasync16(sb + 2 * SMATA + so,         wkhi + gB);
            cpasync16(sb + 2 * SMATA + SMATB + so, wklo + gB);
        }
        asm volatile("cp.async.commit_group;" ::: "memory");
    };

    float acc[2][8][4];
#pragma unroll
    for (int mt = 0; mt < 2; ++mt)
#pragma unroll
        for (int nt = 0; nt < 8; ++nt)
#pragma unroll
            for (int q = 0; q < 4; ++q) acc[mt][nt][q] = 0.f;

    load_chunk(0);

    for (int c = 0; c < 4; ++c) {
        if (c + 1 < 4) {
            load_chunk(c + 1);
            asm volatile("cp.async.wait_group 1;" ::: "memory");
        } else {
            asm volatile("cp.async.wait_group 0;" ::: "memory");
        }
        __syncthreads();

        uint32_t sb = dbase + (uint32_t)(c & 1) * SBUF;
#pragma unroll
        for (int ks = 0; ks < 2; ++ks) {
            const uint32_t cb = (uint32_t)((ks * 16 + t2) * 2);
            uint32_t a_h[2][4], a_l[2][4];
#pragma unroll
            for (int mt = 0; mt < 2; ++mt) {
                uint32_t r0 = sb + (uint32_t)((warpM + mt * 16 + g) * 80) + cb;
                uint32_t r8 = r0 + 8 * 80;
                a_h[mt][0] = lds32(r0);         a_h[mt][1] = lds32(r8);
                a_h[mt][2] = lds32(r0 + 16);    a_h[mt][3] = lds32(r8 + 16);
                a_l[mt][0] = lds32(r0 + SMATA); a_l[mt][1] = lds32(r8 + SMATA);
                a_l[mt][2] = lds32(r0 + SMATA + 16); a_l[mt][3] = lds32(r8 + SMATA + 16);
            }
            uint32_t b_h[8][2], b_l[8][2];
#pragma unroll
            for (int nt = 0; nt < 8; ++nt) {
                uint32_t rr = sb + 2 * SMATA + (uint32_t)((nt * 8 + g) * 80) + cb;
                b_h[nt][0] = lds32(rr);          b_h[nt][1] = lds32(rr + 16);
                b_l[nt][0] = lds32(rr + SMATB);  b_l[nt][1] = lds32(rr + SMATB + 16);
            }
#pragma unroll
            for (int mt = 0; mt < 2; ++mt)
#pragma unroll
                for (int nt = 0; nt < 8; ++nt) {
                    mma16816(acc[mt][nt], a_h[mt], b_h[nt]);
                    mma16816(acc[mt][nt], a_h[mt], b_l[nt]);
                    mma16816(acc[mt][nt], a_l[mt], b_h[nt]);
                }
        }
        __syncthreads();
    }

#pragma unroll
    for (int mt = 0; mt < 2; ++mt) {
#pragma unroll
        for (int hf = 0; hf < 2; ++hf) {
            int row = m0 + warpM + mt * 16 + g + hf * 8;
            float v[16];
#pragma unroll
            for (int nt = 0; nt < 8; ++nt) {
                int c0 = nt * 8 + t2;
                v[2 * nt]     = (c0     < NN) ? acc[mt][nt][2 * hf]     : -1e30f;
                v[2 * nt + 1] = (c0 + 1 < NN) ? acc[mt][nt][2 * hf + 1] : -1e30f;
            }
            float mx = v[0];
#pragma unroll
            for (int q = 1; q < 16; ++q) mx = fmaxf(mx, v[q]);
            mx = fmaxf(mx, __shfl_xor_sync(0xffffffffu, mx, 1));
            mx = fmaxf(mx, __shfl_xor_sync(0xffffffffu, mx, 2));
            float sum = 0.f;
#pragma unroll
            for (int q = 0; q < 16; ++q) { v[q] = __expf(v[q] - mx); sum += v[q]; }
            sum += __shfl_xor_sync(0xffffffffu, sum, 1);
            sum += __shfl_xor_sync(0xffffffffu, sum, 2);
            float inv = __fdividef(1.f, sum);
            float* op = S + (size_t)row * NN;
#pragma unroll
            for (int nt = 0; nt < 8; ++nt) {
                int c0 = nt * 8 + t2;
                if (c0 < NN)
                    *reinterpret_cast<float2*>(op + c0) =
                        make_float2(v[2 * nt] * inv, v[2 * nt + 1] * inv);
            }
        }
    }
}

// =======================================================================================
// HMMA bf16 hi/lo 3-pass GEMM, dual-target (R7-proven).
// =======================================================================================
#define MATB 10240u
#define BUFB 40960u

__global__ void __launch_bounds__(256)
gemm_hmma(const __nv_bfloat16* __restrict__ a1hi, const __nv_bfloat16* __restrict__ a1lo,
          int lda1, int k1len,
          const __nv_bfloat16* __restrict__ a2hi, const __nv_bfloat16* __restrict__ a2lo,
          int lda2, int K,
          const __nv_bfloat16* __restrict__ w0hi, const __nv_bfloat16* __restrict__ w0lo,
          const float* __restrict__ b0, float* __restrict__ C0, int act0,
          const __nv_bfloat16* __restrict__ w1hi, const __nv_bfloat16* __restrict__ w1lo,
          const float* __restrict__ b1, float* __restrict__ C1, int act1,
          int nsplit)
{
    extern __shared__ __align__(16) char dsm[];
    const uint32_t dbase = smem_u32(dsm);

    const int tid = threadIdx.x;
    const int m0 = blockIdx.y * 128;
    const int nb = blockIdx.x;

    const __nv_bfloat16 *whi, *wlo; const float* bias; float* C; int act, nloc;
    if (nb < nsplit) { whi = w0hi; wlo = w0lo; bias = b0; C = C0; act = act0; nloc = nb * 128; }
    else             { whi = w1hi; wlo = w1lo; bias = b1; C = C1; act = act1; nloc = (nb - nsplit) * 128; }

    const int wid = tid >> 5;
    const int lane = tid & 31;
    const int g  = lane >> 2;
    const int t2 = (lane & 3) * 2;
    const int warpM = (wid & 3) * 32;
    const int warpN = (wid >> 2) * 64;

    const int nch = K / 32;

    auto load_chunk = [&](int c) {
        uint32_t sb = dbase + (uint32_t)(c & 1) * BUFB;
        int k0 = c * 32;
        const __nv_bfloat16 *shi, *slo; int ld, kk;
        if (k0 < k1len) { shi = a1hi; slo = a1lo; ld = lda1; kk = k0; }
        else            { shi = a2hi; slo = a2lo; ld = lda2; kk = k0 - k1len; }
#pragma unroll
        for (int i = 0; i < 2; ++i) {
            int gidx = tid + 256 * i;
            int row = gidx >> 2, seg = gidx & 3;
            uint32_t so = (uint32_t)(row * 80 + seg * 16);
            size_t gA = (size_t)(m0 + row) * ld + kk + seg * 8;
            cpasync16(sb + so,            shi + gA);
            cpasync16(sb + MATB + so,     slo + gA);
            size_t gB = (size_t)(nloc + row) * K + k0 + seg * 8;
            cpasync16(sb + 2 * MATB + so, whi + gB);
            cpasync16(sb + 3 * MATB + so, wlo + gB);
        }
        asm volatile("cp.async.commit_group;" ::: "memory");
    };

    float acc[2][8][4];
#pragma unroll
    for (int mt = 0; mt < 2; ++mt)
#pragma unroll
        for (int nt = 0; nt < 8; ++nt)
#pragma unroll
            for (int q = 0; q < 4; ++q) acc[mt][nt][q] = 0.f;

    load_chunk(0);

    for (int c = 0; c < nch; ++c) {
        if (c + 1 < nch) {
            load_chunk(c + 1);
            asm volatile("cp.async.wait_group 1;" ::: "memory");
        } else {
            asm volatile("cp.async.wait_group 0;" ::: "memory");
        }
        __syncthreads();

        uint32_t sb = dbase + (uint32_t)(c & 1) * BUFB;
#pragma unroll
        for (int ks = 0; ks < 2; ++ks) {
            const uint32_t cb = (uint32_t)((ks * 16 + t2) * 2);
            uint32_t a_h[2][4], a_l[2][4];
#pragma unroll
            for (int mt = 0; mt < 2; ++mt) {
                uint32_t r0 = sb + (uint32_t)((warpM + mt * 16 + g) * 80) + cb;
                uint32_t r8 = r0 + 8 * 80;
                a_h[mt][0] = lds32(r0);        a_h[mt][1] = lds32(r8);
                a_h[mt][2] = lds32(r0 + 16);   a_h[mt][3] = lds32(r8 + 16);
                a_l[mt][0] = lds32(r0 + MATB); a_l[mt][1] = lds32(r8 + MATB);
                a_l[mt][2] = lds32(r0 + MATB + 16); a_l[mt][3] = lds32(r8 + MATB + 16);
            }
            uint32_t b_h[8][2], b_l[8][2];
#pragma unroll
            for (int nt = 0; nt < 8; ++nt) {
                uint32_t rr = sb + 2 * MATB + (uint32_t)((warpN + nt * 8 + g) * 80) + cb;
                b_h[nt][0] = lds32(rr);        b_h[nt][1] = lds32(rr + 16);
                b_l[nt][0] = lds32(rr + MATB); b_l[nt][1] = lds32(rr + MATB + 16);
            }
#pragma unroll
            for (int mt = 0; mt < 2; ++mt)
#pragma unroll
                for (int nt = 0; nt < 8; ++nt) {
                    mma16816(acc[mt][nt], a_h[mt], b_h[nt]);
                    mma16816(acc[mt][nt], a_h[mt], b_l[nt]);
                    mma16816(acc[mt][nt], a_l[mt], b_h[nt]);
                }
        }
        __syncthreads();
    }

#pragma unroll
    for (int mt = 0; mt < 2; ++mt) {
        int r0 = m0 + warpM + mt * 16 + g;
#pragma unroll
        for (int nt = 0; nt < 8; ++nt) {
            int cc = nloc + warpN + nt * 8 + t2;
            float bb0 = bias[cc], bb1 = bias[cc + 1];
            float v0 = acc[mt][nt][0] + bb0, v1 = acc[mt][nt][1] + bb1;
            float v2 = acc[mt][nt][2] + bb0, v3 = acc[mt][nt][3] + bb1;
            if (act == 0) {
                v0 = __fdividef(1.f, 1.f + __expf(-v0));
                v1 = __fdividef(1.f, 1.f + __expf(-v1));
                v2 = __fdividef(1.f, 1.f + __expf(-v2));
                v3 = __fdividef(1.f, 1.f + __expf(-v3));
            } else {
                v0 = tanhf(v0); v1 = tanhf(v1); v2 = tanhf(v2); v3 = tanhf(v3);
            }
            *reinterpret_cast<float2*>(&C[(size_t)r0 * 256 + cc])       = make_float2(v0, v1);
            *reinterpret_cast<float2*>(&C[(size_t)(r0 + 8) * 256 + cc]) = make_float2(v2, v3);
        }
    }
}

// =======================================================================================
// Scan, warp-autonomous: each warp owns 32 columns and a PRIVATE 16-slot score ring
// (lanes 0..24 cp.async 8B each). No __syncthreads — only per-warp wait+__syncwarp.
// Groups of 4 steps; e/a in a 3-buffer register pipeline.
// =======================================================================================
__global__ void __launch_bounds__(256) scan_kernel(const float* __restrict__ S,
                                                   const float* __restrict__ E,
                                                   const float* __restrict__ A,
                                                   const float* __restrict__ M0,
                                                   __nv_bfloat16* __restrict__ Rhi,
                                                   __nv_bfloat16* __restrict__ Rlo)
{
    const int b = blockIdx.x;
    const int d = threadIdx.x;
    const int w = d >> 5;
    const int lane = d & 31;
    __shared__ __align__(16) float ring[8][16][52];

    u64 m[25];
#pragma unroll
    for (int j = 0; j < 25; ++j)
        m[j] = pack2(M0[(2 * j) * DV + d], M0[(2 * j + 1) * DV + d]);

    const float* sp = S + (size_t)b * LL * NN;
    const float* ep = E + (size_t)b * LL * DV + d;
    const float* ap = A + (size_t)b * LL * DV + d;
    __nv_bfloat16* rh = Rhi + (size_t)b * LL * DV + d;
    __nv_bfloat16* rl = Rlo + (size_t)b * LL * DV + d;

    // per-warp score slot loader: lanes 0..24 fetch floats (2*lane, 2*lane+1)
    auto fetch_slot = [&](int slot, int l) {
        if (lane < 25)
            cpasync8(smem_u32(&ring[w][slot][lane * 2]), sp + (size_t)l * NN + lane * 2);
    };

    // preload groups 0 and 1 (steps 0..7)
#pragma unroll
    for (int st = 0; st < 4; ++st) fetch_slot(st, st);
    asm volatile("cp.async.commit_group;" ::: "memory");
#pragma unroll
    for (int st = 0; st < 4; ++st) fetch_slot(4 + st, 4 + st);
    asm volatile("cp.async.commit_group;" ::: "memory");
    asm volatile("cp.async.wait_group 1;" ::: "memory");

    float ecur[4], acur[4], enx[4], anx[4];
#pragma unroll
    for (int st = 0; st < 4; ++st) { ecur[st] = ep[(size_t)st * DV]; acur[st] = ap[(size_t)st * DV]; }
#pragma unroll
    for (int st = 0; st < 4; ++st) { enx[st] = ep[(size_t)(4 + st) * DV]; anx[st] = ap[(size_t)(4 + st) * DV]; }
    __syncwarp();

    for (int gi = 0; gi < LL / 4; ++gi) {
        const int base = gi * 4;
        // prefetch scores for group gi+2
#pragma unroll
        for (int st = 0; st < 4; ++st) {
            int ll = base + 8 + st; if (ll > LL - 1) ll = LL - 1;
            fetch_slot((base + 8 + st) & 15, ll);
        }
        asm volatile("cp.async.commit_group;" ::: "memory");
        // prefetch e/a for group gi+2
        float etmp[4], atmp[4];
#pragma unroll
        for (int st = 0; st < 4; ++st) {
            int ll = base + 8 + st; if (ll > LL - 1) ll = LL - 1;
            etmp[st] = ep[(size_t)ll * DV];
            atmp[st] = ap[(size_t)ll * DV];
        }

        // process 4 steps back-to-back
#pragma unroll
        for (int st = 0; st < 4; ++st) {
            const int l = base + st;
            u64 apk  = pack2(acur[st], acur[st]);
            u64 nepk = pack2(-ecur[st], -ecur[st]);
            u64 r0 = 0ull, r1 = 0ull;
            const u64* sb = reinterpret_cast<const u64*>(ring[w][l & 15]);
#pragma unroll
            for (int j = 0; j < 25; ++j) {
                u64 spk = sb[j];                 // LDS.64 broadcast within warp
                if (j & 1) r1 = fma2(spk, m[j], r1);
                else       r0 = fma2(spk, m[j], r0);
                u64 tt = fma2(nepk, m[j], apk);
                m[j] = fma2(spk, tt, m[j]);
            }
            float2 rv = unpack2(add2(r0, r1));
            float rr = rv.x + rv.y;
            __nv_bfloat16 h  = __float2bfloat16(rr);
            __nv_bfloat16 lo = __float2bfloat16(rr - __bfloat162float(h));
            rh[(size_t)l * DV] = h;
            rl[(size_t)l * DV] = lo;
        }

        asm volatile("cp.async.wait_group 1;" ::: "memory");
        __syncwarp();
#pragma unroll
        for (int st = 0; st < 4; ++st) {
            ecur[st] = enx[st]; acur[st] = anx[st];
            enx[st] = etmp[st]; anx[st] = atmp[st];
        }
    }
}

// =======================================================================================
// Launch
// =======================================================================================
extern "C" void kernel_launch(void* const* d_in, const int* in_sizes, int n_in,
                              void* d_out, int out_size)
{
    const float* problems     = (const float*)d_in[0];
    const float* interactions = (const float*)d_in[1];
    const float* w_key        = (const float*)d_in[2];
    const float* w_erase_w    = (const float*)d_in[3];
    const float* w_erase_b    = (const float*)d_in[4];
    const float* w_add_w      = (const float*)d_in[5];
    const float* w_add_b      = (const float*)d_in[6];
    const float* w_out_w      = (const float*)d_in[7];
    const float* w_out_b      = (const float*)d_in[8];
    const float* init_memory  = (const float*)d_in[9];
    float* out = (float*)d_out;

    float *ge, *ga, *gs;
    __nv_bfloat16 *ibhi, *iblo, *pbhi, *pblo, *rhi, *rlo;
    __nv_bfloat16 *wehi, *welo, *wahi, *walo, *wohi, *wolo, *wkhi, *wklo;
    cudaGetSymbolAddress((void**)&ge,   g_e);
    cudaGetSymbolAddress((void**)&ga,   g_a);
    cudaGetSymbolAddress((void**)&gs,   g_score);
    cudaGetSymbolAddress((void**)&ibhi, g_ibhi);  cudaGetSymbolAddress((void**)&iblo, g_iblo);
    cudaGetSymbolAddress((void**)&pbhi, g_pbhi);  cudaGetSymbolAddress((void**)&pblo, g_pblo);
    cudaGetSymbolAddress((void**)&rhi,  g_rhi);   cudaGetSymbolAddress((void**)&rlo,  g_rlo);
    cudaGetSymbolAddress((void**)&wehi, g_wehi);  cudaGetSymbolAddress((void**)&welo, g_welo);
    cudaGetSymbolAddress((void**)&wahi, g_wahi);  cudaGetSymbolAddress((void**)&walo, g_walo);
    cudaGetSymbolAddress((void**)&wohi, g_wohi);  cudaGetSymbolAddress((void**)&wolo, g_wolo);
    cudaGetSymbolAddress((void**)&wkhi, g_wkhi);  cudaGetSymbolAddress((void**)&wklo, g_wklo);

    cudaFuncSetAttribute(gemm_hmma, cudaFuncAttributeMaxDynamicSharedMemorySize, 2 * BUFB);
    cudaFuncSetAttribute(score_hmma, cudaFuncAttributeMaxDynamicSharedMemorySize, 2 * SBUF);

    // conversions (f32 -> bf16 hi/lo): two big activations + one fused weight launch
    conv_kernel<<<(MM * DV / 4 + 255) / 256, 256>>>(interactions, ibhi, iblo, MM * DV / 4);
    conv_kernel<<<(MM * DK / 4 + 255) / 256, 256>>>(problems, pbhi, pblo, MM * DK / 4);
    {
        int n0 = DV * DV / 4, n1 = DV * DV / 4, n2 = HH * (DV + DK) / 4, n3 = NN * DK / 4;
        int nt = n0 + n1 + n2 + n3;
        conv_w_kernel<<<(nt + 255) / 256, 256>>>(w_erase_w, wehi, welo, n0,
                                                 w_add_w,   wahi, walo, n1,
                                                 w_out_w,   wohi, wolo, n2,
                                                 w_key,     wkhi, wklo, n3);
    }

    // attention scores (HMMA + softmax epilogue)
    score_hmma<<<MM / 128, 128, 2 * SBUF>>>(pbhi, pblo, wkhi, wklo, gs);

    // merged gate GEMMs: n-targets {e:0,1, a:2,3} share each A m-block through L2
    dim3 gg(4, MM / 128);
    gemm_hmma<<<gg, 256, 2 * BUFB>>>(ibhi, iblo, DV, DV, ibhi, iblo, DV, DV,
                                     wehi, welo, w_erase_b, ge, /*sigmoid*/0,
                                     wahi, walo, w_add_b,   ga, /*tanh*/1, 2);

    // sequential memory scan (warp-autonomous)
    scan_kernel<<<BB, 256>>>(gs, ge, ga, init_memory, rhi, rlo);

    // output GEMM: A = [reads(256) | problems(128)], K = 384; n-blocks fast for A reuse
    dim3 go(2, MM / 128);
    gemm_hmma<<<go, 256, 2 * BUFB>>>(rhi, rlo, DV, DV, pbhi, pblo, DK, DV + DK,
                                     wohi, wolo, w_out_b, out, /*tanh*/1,
                                     wohi, wolo, w_out_b, out, 1, 2);
}